// round 5
// baseline (speedup 1.0000x reference)
#include <cuda_runtime.h>
#include <math.h>

#define B     64
#define T     512
#define NSTEP 128
#define S     512
#define H2D   512
#define ATT   128
#define NCLS  64
#define GRID  148
#define NTH   512
#define KC    32            // k-chunk width
#define NCH   32            // 1024 / KC

typedef unsigned long long ull;

// ---------------- scratch (static device globals; no allocation) ----------------
__device__ float g_psi[B * T * ATT];
__device__ float g_h1[2][B * S];
__device__ float g_h2[2][B * S];
__device__ float g_c1[B * S];
__device__ float g_c2[B * S];
__device__ float g_ctx[B * H2D];
__device__ unsigned g_cnt1[8];
__device__ unsigned g_cnt2;
__device__ volatile unsigned g_epoch;

__device__ __forceinline__ float tanh_fast(float v)
{
    float r;
    asm("tanh.approx.f32 %0, %1;" : "=f"(r) : "f"(v));
    return r;
}
__device__ __forceinline__ float sigf(float v) { return 0.5f * tanh_fast(0.5f * v) + 0.5f; }

__device__ __forceinline__ ull fma2(ull a, ull b, ull c)
{
    ull d;
    asm("fma.rn.f32x2 %0, %1, %2, %3;" : "=l"(d) : "l"(a), "l"(b), "l"(c));
    return d;
}
__device__ __forceinline__ ull add2(ull a, ull b)
{
    ull d;
    asm("add.rn.f32x2 %0, %1, %2;" : "=l"(d) : "l"(a), "l"(b));
    return d;
}
__device__ __forceinline__ ull dup2(float a)
{
    ull d;
    asm("mov.b64 %0, {%1, %1};" : "=l"(d) : "f"(a));
    return d;
}

// -------- two-level grid barrier (148 co-resident CTAs) ------------------------
__device__ __forceinline__ void gbar(unsigned& phase, int cta)
{
    __syncthreads();
    if (threadIdx.x == 0) {
        ++phase;
        __threadfence();
        int grp = cta & 7;
        unsigned gsz = 18u + (grp < 4 ? 1u : 0u);   // 148 = 4*19 + 4*18
        if (atomicAdd(&g_cnt1[grp], 1u) == gsz - 1u) {
            g_cnt1[grp] = 0u;
            __threadfence();
            if (atomicAdd(&g_cnt2, 1u) == 7u) {
                g_cnt2 = 0u;
                __threadfence();
                g_epoch = phase;
            } else {
                while (g_epoch != phase) {}
            }
        } else {
            while (g_epoch != phase) {}
        }
        __threadfence();
    }
    __syncthreads();
}

// ---------------- smem overlay ----------------
struct SmL {                       // GEMM staging (26.6 KB)
    ull   A2[2][KC][18];           // [stage][k][row] duplicated pairs {a,a}
    float Bs[2][KC][68];           // [stage][k][batch]
};
struct SmR {                       // reduction (41.2 KB)
    float red[8][32 * 36];         // [warp][lane*36 + j]
    float gates[16][68];           // [gaterow][batch]
};
struct SmA {                       // attention (~6.8 KB)
    float vec[1024]; float phi[128]; float al[512]; float red[32];
};
union SmU { SmL g; SmR r; SmA a; };

// -------- fused LSTM: 4 units x 64 batches, full K=1024, in-CTA reduce + gates --
__device__ __forceinline__ void lstm_fused(SmU* sm, int cta, int tid,
        const float* __restrict__ Wih, int pIh, int colOff,
        const float* __restrict__ Whh,
        const float* __restrict__ z0, const float* __restrict__ z1,
        const float* __restrict__ bih, const float* __restrict__ bhh,
        float* __restrict__ cst, float* __restrict__ hout,
        const int* __restrict__ x, int t, int onehot)
{
    if (cta >= 128) return;
    int u0   = cta << 2;
    int wid  = tid >> 5;
    int lane = tid & 31;
    int tr4  = (lane >> 3) << 2;    // rows tr4..tr4+3
    int tc8  = (lane & 7) << 3;     // batches tc8..tc8+7
    int kw   = wid << 1;            // this warp's 2 k-offsets per chunk

    // loader indices
    int arow = tid >> 5;            // 0..15
    int aka  = tid & 31;
    int agrow = (arow >> 2) * 512 + u0 + (arow & 3);
    int bb   = tid >> 3;            // 0..63
    int bkq  = tid & 7;

    ull acc[4][4];
#pragma unroll
    for (int i = 0; i < 4; ++i)
#pragma unroll
        for (int j = 0; j < 4; ++j) acc[i][j] = 0ull;

    auto ldgA = [&](int c) -> float {
        int col = c * KC + aka;
        return (col < 512) ? Wih[(size_t)agrow * pIh + colOff + col]
                           : Whh[(size_t)agrow * 512 + col - 512];
    };
    auto ldgB = [&](int c) -> float4 {
        const float* src = (c < 16) ? z0 + bb * 512 + c * KC
                                    : z1 + bb * 512 + (c - 16) * KC;
        return *(const float4*)&src[bkq * 4];
    };

    float  af = ldgA(0);
    float4 bf = ldgB(0);
    sm->g.A2[0][aka][arow] = dup2(af);
    sm->g.Bs[0][bkq * 4 + 0][bb] = bf.x;
    sm->g.Bs[0][bkq * 4 + 1][bb] = bf.y;
    sm->g.Bs[0][bkq * 4 + 2][bb] = bf.z;
    sm->g.Bs[0][bkq * 4 + 3][bb] = bf.w;
    __syncthreads();

    for (int c = 0; c < NCH; ++c) {
        int st = c & 1;
        if (c < NCH - 1) { af = ldgA(c + 1); bf = ldgB(c + 1); }
#pragma unroll
        for (int q = 0; q < 2; ++q) {
            int k = kw + q;
            ulonglong2 a01 = *(const ulonglong2*)&sm->g.A2[st][k][tr4];
            ulonglong2 a23 = *(const ulonglong2*)&sm->g.A2[st][k][tr4 + 2];
            ulonglong2 b01 = *(const ulonglong2*)&sm->g.Bs[st][k][tc8];
            ulonglong2 b23 = *(const ulonglong2*)&sm->g.Bs[st][k][tc8 + 4];
            acc[0][0] = fma2(a01.x, b01.x, acc[0][0]);
            acc[0][1] = fma2(a01.x, b01.y, acc[0][1]);
            acc[0][2] = fma2(a01.x, b23.x, acc[0][2]);
            acc[0][3] = fma2(a01.x, b23.y, acc[0][3]);
            acc[1][0] = fma2(a01.y, b01.x, acc[1][0]);
            acc[1][1] = fma2(a01.y, b01.y, acc[1][1]);
            acc[1][2] = fma2(a01.y, b23.x, acc[1][2]);
            acc[1][3] = fma2(a01.y, b23.y, acc[1][3]);
            acc[2][0] = fma2(a23.x, b01.x, acc[2][0]);
            acc[2][1] = fma2(a23.x, b01.y, acc[2][1]);
            acc[2][2] = fma2(a23.x, b23.x, acc[2][2]);
            acc[2][3] = fma2(a23.x, b23.y, acc[2][3]);
            acc[3][0] = fma2(a23.y, b01.x, acc[3][0]);
            acc[3][1] = fma2(a23.y, b01.y, acc[3][1]);
            acc[3][2] = fma2(a23.y, b23.x, acc[3][2]);
            acc[3][3] = fma2(a23.y, b23.y, acc[3][3]);
        }
        if (c < NCH - 1) {
            int sn = st ^ 1;
            sm->g.A2[sn][aka][arow] = dup2(af);
            sm->g.Bs[sn][bkq * 4 + 0][bb] = bf.x;
            sm->g.Bs[sn][bkq * 4 + 1][bb] = bf.y;
            sm->g.Bs[sn][bkq * 4 + 2][bb] = bf.z;
            sm->g.Bs[sn][bkq * 4 + 3][bb] = bf.w;
        }
        __syncthreads();
    }

    // cross-warp k reduction: 16 -> 8 -> 4 -> 2 -> 1 (elementwise on lane tiles)
#pragma unroll
    for (int half = 8; half >= 1; half >>= 1) {
        if (wid >= half && wid < 2 * half) {
            float* dst = &sm->r.red[wid - half][lane * 36];
#pragma unroll
            for (int i = 0; i < 4; ++i) {
                *(ulonglong2*)&dst[i * 8]     = make_ulonglong2(acc[i][0], acc[i][1]);
                *(ulonglong2*)&dst[i * 8 + 4] = make_ulonglong2(acc[i][2], acc[i][3]);
            }
        }
        __syncthreads();
        if (wid < half) {
            const float* src = &sm->r.red[wid][lane * 36];
#pragma unroll
            for (int i = 0; i < 4; ++i) {
                ulonglong2 v0 = *(const ulonglong2*)&src[i * 8];
                ulonglong2 v1 = *(const ulonglong2*)&src[i * 8 + 4];
                acc[i][0] = add2(acc[i][0], v0.x);
                acc[i][1] = add2(acc[i][1], v0.y);
                acc[i][2] = add2(acc[i][2], v1.x);
                acc[i][3] = add2(acc[i][3], v1.y);
            }
        }
        __syncthreads();
    }

    // warp 0 holds full sums; write gate rows to smem
    if (wid == 0) {
#pragma unroll
        for (int i = 0; i < 4; ++i) {
            *(ulonglong2*)&sm->r.gates[tr4 + i][tc8]     = make_ulonglong2(acc[i][0], acc[i][1]);
            *(ulonglong2*)&sm->r.gates[tr4 + i][tc8 + 4] = make_ulonglong2(acc[i][2], acc[i][3]);
        }
    }
    __syncthreads();

    // epilogue: 256 threads = 64 batches x 4 units
    if (tid < 256) {
        int b = tid >> 2, ul = tid & 3;
        int unit = u0 + ul;
        float pre[4];
#pragma unroll
        for (int g = 0; g < 4; ++g) {
            int grow = g * 512 + unit;
            pre[g] = sm->r.gates[g * 4 + ul][b] + bih[grow] + bhh[grow];
        }
        if (onehot) {
            int cls = x[b * NSTEP + t];
#pragma unroll
            for (int g = 0; g < 4; ++g)
                pre[g] += Wih[(size_t)(g * 512 + unit) * pIh + cls];
        }
        float co = cst[b * S + unit];
        float cn = sigf(pre[1]) * co + sigf(pre[0]) * tanh_fast(pre[2]);
        float hn = sigf(pre[3]) * tanh_fast(cn);
        cst[b * S + unit]  = cn;
        hout[b * S + unit] = hn;
    }
    __syncthreads();
}

// -------- fused attention + output projection, one CTA per batch ----------------
__device__ __forceinline__ void attn_phase(SmA* a, int cta, int tid,
        const float* __restrict__ h,
        const float* __restrict__ Wphi, const float* __restrict__ bphi,
        const float* __restrict__ Wcd,  const float* __restrict__ bcd,
        const float* __restrict__ h2v, float* __restrict__ out, int t)
{
    if (cta >= B) return;
    int b    = cta;
    int wid  = tid >> 5;
    int lane = tid & 31;

    a->vec[tid] = h2v[b * S + tid];
    __syncthreads();

#pragma unroll
    for (int i = 0; i < 8; ++i) {
        int aa = wid * 8 + i;
        const float* wr = Wphi + aa * S;
        float sum = 0.f;
#pragma unroll
        for (int idx = lane * 4; idx < S; idx += 128) {
            float4 w4 = *(const float4*)&wr[idx];
            float4 v4 = *(const float4*)&a->vec[idx];
            sum = fmaf(w4.x, v4.x, sum);
            sum = fmaf(w4.y, v4.y, sum);
            sum = fmaf(w4.z, v4.z, sum);
            sum = fmaf(w4.w, v4.w, sum);
        }
#pragma unroll
        for (int o = 16; o > 0; o >>= 1) sum += __shfl_xor_sync(0xffffffffu, sum, o);
        if (lane == 0) a->phi[aa] = sum + bphi[aa];
    }
    __syncthreads();

    float4 p4 = *(const float4*)&a->phi[lane * 4];
    const float* psib = g_psi + (size_t)b * T * ATT;
    for (int tt = wid * 32; tt < wid * 32 + 32; ++tt) {
        float4 v = *(const float4*)&psib[tt * ATT + lane * 4];
        float sum = p4.x * v.x + p4.y * v.y + p4.z * v.z + p4.w * v.w;
#pragma unroll
        for (int o = 16; o > 0; o >>= 1) sum += __shfl_xor_sync(0xffffffffu, sum, o);
        if (lane == 0) a->al[tt] = sum;
    }
    __syncthreads();

    float e = a->al[tid];
    float m = e;
#pragma unroll
    for (int o = 16; o > 0; o >>= 1) m = fmaxf(m, __shfl_xor_sync(0xffffffffu, m, o));
    if (lane == 0) a->red[wid] = m;
    __syncthreads();
    if (tid == 0) {
        float mm = a->red[0];
        for (int i = 1; i < 16; ++i) mm = fmaxf(mm, a->red[i]);
        a->red[16] = mm;
    }
    __syncthreads();
    m = a->red[16];
    float ex = __expf(e - m);
    a->al[tid] = ex;
    float ssum = ex;
#pragma unroll
    for (int o = 16; o > 0; o >>= 1) ssum += __shfl_xor_sync(0xffffffffu, ssum, o);
    if (lane == 0) a->red[wid] = ssum;
    __syncthreads();
    if (tid == 0) {
        float s = 0.f;
        for (int i = 0; i < 16; ++i) s += a->red[i];
        a->red[17] = 1.f / s;
    }
    __syncthreads();
    float inv = a->red[17];

    {
        const float* hb = h + (size_t)b * T * H2D;
        float acc = 0.f;
#pragma unroll 16
        for (int tt = 0; tt < T; ++tt)
            acc = fmaf(a->al[tt], hb[tt * H2D + tid], acc);
        float cv = acc * inv;
        a->vec[S + tid] = cv;
        g_ctx[b * H2D + tid] = cv;
    }
    __syncthreads();

#pragma unroll
    for (int i = 0; i < 4; ++i) {
        int c = wid * 4 + i;
        const float* wr = Wcd + c * (S + H2D);
        float sum = 0.f;
#pragma unroll
        for (int idx = lane * 4; idx < S + H2D; idx += 128) {
            float4 w4 = *(const float4*)&wr[idx];
            float4 v4 = *(const float4*)&a->vec[idx];
            sum = fmaf(w4.x, v4.x, sum);
            sum = fmaf(w4.y, v4.y, sum);
            sum = fmaf(w4.z, v4.z, sum);
            sum = fmaf(w4.w, v4.w, sum);
        }
#pragma unroll
        for (int o = 16; o > 0; o >>= 1) sum += __shfl_xor_sync(0xffffffffu, sum, o);
        if (lane == 0) out[((size_t)b * NSTEP + t) * NCLS + c] = sum + bcd[c];
    }
    __syncthreads();
}

// ---------------- psi_h precompute ----------------
__global__ void k_psi(const float* __restrict__ h,
                      const float* __restrict__ Wpsi,
                      const float* __restrict__ bpsi)
{
    __shared__ __align__(16) float hs[32][36];
    __shared__ __align__(16) float ws[128][36];
    int b   = blockIdx.y;
    int t0  = blockIdx.x * 32;
    int tid = threadIdx.x;
    int tg  = tid & 7;
    int ag  = tid >> 3;

    float acc[16];
#pragma unroll
    for (int i = 0; i < 16; ++i) acc[i] = 0.f;

    for (int dc = 0; dc < H2D; dc += 32) {
#pragma unroll
        for (int i = 0; i < 4; ++i) {
            int lin = tid + i * 256;
            int r = lin >> 5, c = lin & 31;
            hs[r][c] = h[((size_t)b * T + t0 + r) * H2D + dc + c];
        }
#pragma unroll
        for (int i = 0; i < 16; ++i) {
            int lin = tid + i * 256;
            int r = lin >> 5, c = lin & 31;
            ws[r][c] = Wpsi[r * H2D + dc + c];
        }
        __syncthreads();
#pragma unroll
        for (int k = 0; k < 32; k += 4) {
            float4 hv[4], wv[4];
#pragma unroll
            for (int j = 0; j < 4; ++j) hv[j] = *(const float4*)&hs[tg * 4 + j][k];
#pragma unroll
            for (int j = 0; j < 4; ++j) wv[j] = *(const float4*)&ws[ag * 4 + j][k];
#pragma unroll
            for (int i = 0; i < 4; ++i)
#pragma unroll
                for (int j = 0; j < 4; ++j) {
                    acc[i * 4 + j] = fmaf(hv[i].x, wv[j].x, acc[i * 4 + j]);
                    acc[i * 4 + j] = fmaf(hv[i].y, wv[j].y, acc[i * 4 + j]);
                    acc[i * 4 + j] = fmaf(hv[i].z, wv[j].z, acc[i * 4 + j]);
                    acc[i * 4 + j] = fmaf(hv[i].w, wv[j].w, acc[i * 4 + j]);
                }
        }
        __syncthreads();
    }
#pragma unroll
    for (int i = 0; i < 4; ++i)
#pragma unroll
        for (int j = 0; j < 4; ++j) {
            int tt = t0 + tg * 4 + i;
            int a  = ag * 4 + j;
            g_psi[((size_t)b * T + tt) * ATT + a] = acc[i * 4 + j] + bpsi[a];
        }
}

// ---------------- persistent mega kernel ----------------
__global__ void __launch_bounds__(NTH, 1) k_mega(
        const int* __restrict__ x, const float* __restrict__ h,
        const float* __restrict__ Wih0, const float* __restrict__ Whh0,
        const float* __restrict__ bih0, const float* __restrict__ bhh0,
        const float* __restrict__ Wih1, const float* __restrict__ Whh1,
        const float* __restrict__ bih1, const float* __restrict__ bhh1,
        const float* __restrict__ Wphi, const float* __restrict__ bphi,
        const float* __restrict__ Wcd,  const float* __restrict__ bcd,
        float* __restrict__ out)
{
    __shared__ SmU sm;

    int cta = blockIdx.x;
    int tid = threadIdx.x;
    unsigned phase = 0;
    if (tid == 0) phase = g_epoch;

    if (cta < B) {
        int b = cta;
        g_ctx[b * S + tid]   = h[(size_t)b * T * H2D + tid];
        g_h1[0][b * S + tid] = 0.f;
        g_h2[0][b * S + tid] = 0.f;
        g_c1[b * S + tid]    = 0.f;
        g_c2[b * S + tid]    = 0.f;
    }
    gbar(phase, cta);

    for (int t = 0; t < NSTEP; ++t) {
        int par = t & 1;

        // Phase A: LSTM0 (fused GEMM + gates)
        lstm_fused(&sm, cta, tid, Wih0, 576, 64, Whh0,
                   g_ctx, g_h1[par], bih0, bhh0,
                   g_c1, g_h1[par ^ 1], x, t, 1);
        gbar(phase, cta);

        // Phase B: LSTM1
        lstm_fused(&sm, cta, tid, Wih1, 512, 0, Whh1,
                   g_h1[par ^ 1], g_h2[par], bih1, bhh1,
                   g_c2, g_h2[par ^ 1], x, t, 0);
        gbar(phase, cta);

        // Phase C: attention + projection
        attn_phase(&sm.a, cta, tid, h, Wphi, bphi, Wcd, bcd,
                   g_h2[par ^ 1], out, t);
        gbar(phase, cta);
    }
}

// ---------------- launcher ----------------
extern "C" void kernel_launch(void* const* d_in, const int* in_sizes, int n_in,
                              void* d_out, int out_size)
{
    const int*   x    = (const int*)d_in[0];
    const float* h    = (const float*)d_in[1];
    const float* Wih0 = (const float*)d_in[2];
    const float* Whh0 = (const float*)d_in[3];
    const float* bih0 = (const float*)d_in[4];
    const float* bhh0 = (const float*)d_in[5];
    const float* Wih1 = (const float*)d_in[6];
    const float* Whh1 = (const float*)d_in[7];
    const float* bih1 = (const float*)d_in[8];
    const float* bhh1 = (const float*)d_in[9];
    const float* Wphi = (const float*)d_in[10];
    const float* bphi = (const float*)d_in[11];
    const float* Wpsi = (const float*)d_in[12];
    const float* bpsi = (const float*)d_in[13];
    const float* Wcd  = (const float*)d_in[14];
    const float* bcd  = (const float*)d_in[15];
    float* out = (float*)d_out;

    k_psi<<<dim3(T / 32, B), 256>>>(h, Wpsi, bpsi);
    k_mega<<<GRID, NTH>>>(x, h, Wih0, Whh0, bih0, bhh0,
                          Wih1, Whh1, bih1, bhh1,
                          Wphi, bphi, Wcd, bcd, out);
}

// round 6
// speedup vs baseline: 1.5648x; 1.5648x over previous
#include <cuda_runtime.h>
#include <math.h>

#define B     64
#define T     512
#define NSTEP 128
#define S     512
#define H2D   512
#define ATT   128
#define NCLS  64
#define GRID  148
#define NTH   512

typedef unsigned long long ull;

// ---------------- scratch (static device globals; no allocation) ----------------
__device__ float g_psi[B * T * ATT];
__device__ float g_part[32 * 2048 * 64];    // 16 MB K-split partials
__device__ float g_h1[2][B * S];
__device__ float g_h2[2][B * S];
__device__ float g_c1[B * S];
__device__ float g_c2[B * S];
__device__ float g_ctx[B * H2D];
__device__ unsigned g_cnt1[8];
__device__ unsigned g_cnt2;
__device__ volatile unsigned g_epoch;

__device__ __forceinline__ float tanh_fast(float v)
{
    float r;
    asm("tanh.approx.f32 %0, %1;" : "=f"(r) : "f"(v));
    return r;
}
__device__ __forceinline__ float sigf(float v) { return 0.5f * tanh_fast(0.5f * v) + 0.5f; }

__device__ __forceinline__ ull fma2(ull a, ull b, ull c)
{
    ull d;
    asm("fma.rn.f32x2 %0, %1, %2, %3;" : "=l"(d) : "l"(a), "l"(b), "l"(c));
    return d;
}
__device__ __forceinline__ ull dup2(float a)
{
    ull d;
    asm("mov.b64 %0, {%1, %1};" : "=l"(d) : "f"(a));
    return d;
}

// -------- two-level grid barrier (148 co-resident CTAs) ------------------------
__device__ __forceinline__ void gbar(unsigned& phase, int cta)
{
    __syncthreads();
    if (threadIdx.x == 0) {
        ++phase;
        __threadfence();
        int grp = cta & 7;
        unsigned gsz = 18u + (grp < 4 ? 1u : 0u);   // 148 = 4*19 + 4*18
        if (atomicAdd(&g_cnt1[grp], 1u) == gsz - 1u) {
            g_cnt1[grp] = 0u;
            __threadfence();
            if (atomicAdd(&g_cnt2, 1u) == 7u) {
                g_cnt2 = 0u;
                __threadfence();
                g_epoch = phase;
            } else {
                while (g_epoch != phase) {}
            }
        } else {
            while (g_epoch != phase) {}
        }
        __threadfence();
    }
    __syncthreads();
}

// ---------------- smem layout: persistent weight slices + scratch union ---------
struct SmAttn {
    float vec[1024];
    float phi[128];
    float al[512];
    float red[32];
    __align__(16) float part[4][516];
};
struct SmAll {
    float A0[32 * 512];                 // 64 KB persistent LSTM0 weight slice [k][row]
    float A1[32 * 512];                 // 64 KB persistent LSTM1 weight slice
    union {
        float Bs[32][72];               // activation tile [k][batch]
        SmAttn a;
    } u;
};

// -------- GEMM: 512 gate rows x 64 batches x K=32, 8x8 fma2 tiles ---------------
__device__ __forceinline__ void lstm_gemm_phase(SmAll* sm, const float* __restrict__ As,
        int tid, int rg, int sp, const float* __restrict__ z, int koff)
{
    // stage B tile (coalesced gmem: lanes sweep k)
#pragma unroll
    for (int i = 0; i < 4; ++i) {
        int idx = i * 512 + tid;
        int k = idx & 31;
        int b = (idx >> 5) & 63;
        sm->u.Bs[k][b] = z[b * 512 + koff + k];
    }
    __syncthreads();

    int rt = tid >> 3;          // 64 row-tiles of 8
    int bt = tid & 7;           // 8 batch-tiles (4 low + 4 high batches)
    const float* Ab = As + rt * 8;

    ull acc[8][4];
#pragma unroll
    for (int i = 0; i < 8; ++i)
#pragma unroll
        for (int j = 0; j < 4; ++j) acc[i][j] = 0ull;

#pragma unroll 4
    for (int k = 0; k < 32; ++k) {
        float4 a0 = *(const float4*)&Ab[k * 512];
        float4 a1 = *(const float4*)&Ab[k * 512 + 4];
        ulonglong2 bl = *(const ulonglong2*)&sm->u.Bs[k][bt * 4];
        ulonglong2 bh = *(const ulonglong2*)&sm->u.Bs[k][32 + bt * 4];
        ull d;
        d = dup2(a0.x);
        acc[0][0] = fma2(d, bl.x, acc[0][0]); acc[0][1] = fma2(d, bl.y, acc[0][1]);
        acc[0][2] = fma2(d, bh.x, acc[0][2]); acc[0][3] = fma2(d, bh.y, acc[0][3]);
        d = dup2(a0.y);
        acc[1][0] = fma2(d, bl.x, acc[1][0]); acc[1][1] = fma2(d, bl.y, acc[1][1]);
        acc[1][2] = fma2(d, bh.x, acc[1][2]); acc[1][3] = fma2(d, bh.y, acc[1][3]);
        d = dup2(a0.z);
        acc[2][0] = fma2(d, bl.x, acc[2][0]); acc[2][1] = fma2(d, bl.y, acc[2][1]);
        acc[2][2] = fma2(d, bh.x, acc[2][2]); acc[2][3] = fma2(d, bh.y, acc[2][3]);
        d = dup2(a0.w);
        acc[3][0] = fma2(d, bl.x, acc[3][0]); acc[3][1] = fma2(d, bl.y, acc[3][1]);
        acc[3][2] = fma2(d, bh.x, acc[3][2]); acc[3][3] = fma2(d, bh.y, acc[3][3]);
        d = dup2(a1.x);
        acc[4][0] = fma2(d, bl.x, acc[4][0]); acc[4][1] = fma2(d, bl.y, acc[4][1]);
        acc[4][2] = fma2(d, bh.x, acc[4][2]); acc[4][3] = fma2(d, bh.y, acc[4][3]);
        d = dup2(a1.y);
        acc[5][0] = fma2(d, bl.x, acc[5][0]); acc[5][1] = fma2(d, bl.y, acc[5][1]);
        acc[5][2] = fma2(d, bh.x, acc[5][2]); acc[5][3] = fma2(d, bh.y, acc[5][3]);
        d = dup2(a1.z);
        acc[6][0] = fma2(d, bl.x, acc[6][0]); acc[6][1] = fma2(d, bl.y, acc[6][1]);
        acc[6][2] = fma2(d, bh.x, acc[6][2]); acc[6][3] = fma2(d, bh.y, acc[6][3]);
        d = dup2(a1.w);
        acc[7][0] = fma2(d, bl.x, acc[7][0]); acc[7][1] = fma2(d, bl.y, acc[7][1]);
        acc[7][2] = fma2(d, bh.x, acc[7][2]); acc[7][3] = fma2(d, bh.y, acc[7][3]);
    }

    // store partials (batches: low 0..31 via bl-pairs, high 32..63 via bh-pairs)
    int growBase = rg * 512 + rt * 8;
#pragma unroll
    for (int i = 0; i < 8; ++i) {
        float* dst = g_part + (size_t)(sp * 2048 + growBase + i) * 64;
        *(ulonglong2*)&dst[bt * 4]      = make_ulonglong2(acc[i][0], acc[i][1]);
        *(ulonglong2*)&dst[32 + bt * 4] = make_ulonglong2(acc[i][2], acc[i][3]);
    }
}

// -------- epilogue: sum 32 splits + bias (+ one-hot), gates, state update -------
__device__ __forceinline__ void lstm_epi(int cta, int tid,
        const float* __restrict__ Wih, int pIh,
        const float* __restrict__ bih, const float* __restrict__ bhh,
        float* __restrict__ cst, float* __restrict__ hout,
        const int* __restrict__ x, int t, int onehot)
{
    if (cta >= 64) return;
    int id = cta * NTH + tid;
    int u = id >> 6, b = id & 63;
    float pre[4];
#pragma unroll
    for (int g = 0; g < 4; ++g) {
        int row = g * 512 + u;
        float s = bih[row] + bhh[row];
        const float* p = g_part + (size_t)row * 64 + b;
#pragma unroll
        for (int sp = 0; sp < 32; ++sp)
            s += p[(size_t)sp * 2048 * 64];
        pre[g] = s;
    }
    if (onehot) {
        int cls = x[b * NSTEP + t];
#pragma unroll
        for (int g = 0; g < 4; ++g)
            pre[g] += Wih[(size_t)(g * 512 + u) * pIh + cls];
    }
    float co = cst[b * S + u];
    float cn = sigf(pre[1]) * co + sigf(pre[0]) * tanh_fast(pre[2]);
    float hn = sigf(pre[3]) * tanh_fast(cn);
    cst[b * S + u]  = cn;
    hout[b * S + u] = hn;
}

// -------- fused attention + output projection, one CTA per batch ----------------
__device__ __forceinline__ void attn_phase(SmAttn* a, int cta, int tid,
        const float* __restrict__ h,
        const float* __restrict__ Wphi, const float* __restrict__ bphi,
        const float* __restrict__ Wcd,  const float* __restrict__ bcd,
        const float* __restrict__ h2v, float* __restrict__ out, int t)
{
    if (cta >= B) return;
    int b    = cta;
    int wid  = tid >> 5;
    int lane = tid & 31;

    a->vec[tid] = h2v[b * S + tid];
    __syncthreads();

    // phi = Wphi @ h2 + bphi
#pragma unroll
    for (int i = 0; i < 8; ++i) {
        int aa = wid * 8 + i;
        const float* wr = Wphi + aa * S;
        float sum = 0.f;
#pragma unroll
        for (int idx = lane * 4; idx < S; idx += 128) {
            float4 w4 = *(const float4*)&wr[idx];
            float4 v4 = *(const float4*)&a->vec[idx];
            sum = fmaf(w4.x, v4.x, sum);
            sum = fmaf(w4.y, v4.y, sum);
            sum = fmaf(w4.z, v4.z, sum);
            sum = fmaf(w4.w, v4.w, sum);
        }
#pragma unroll
        for (int o = 16; o > 0; o >>= 1) sum += __shfl_xor_sync(0xffffffffu, sum, o);
        if (lane == 0) a->phi[aa] = sum + bphi[aa];
    }
    __syncthreads();

    // e[tt] = phi . psi[b,tt,:]
    float4 p4 = *(const float4*)&a->phi[lane * 4];
    const float* psib = g_psi + (size_t)b * T * ATT;
    for (int tt = wid * 32; tt < wid * 32 + 32; ++tt) {
        float4 v = *(const float4*)&psib[tt * ATT + lane * 4];
        float sum = p4.x * v.x + p4.y * v.y + p4.z * v.z + p4.w * v.w;
#pragma unroll
        for (int o = 16; o > 0; o >>= 1) sum += __shfl_xor_sync(0xffffffffu, sum, o);
        if (lane == 0) a->al[tt] = sum;
    }
    __syncthreads();

    // softmax
    float e = a->al[tid];
    float m = e;
#pragma unroll
    for (int o = 16; o > 0; o >>= 1) m = fmaxf(m, __shfl_xor_sync(0xffffffffu, m, o));
    if (lane == 0) a->red[wid] = m;
    __syncthreads();
    if (tid == 0) {
        float mm = a->red[0];
        for (int i = 1; i < 16; ++i) mm = fmaxf(mm, a->red[i]);
        a->red[16] = mm;
    }
    __syncthreads();
    m = a->red[16];
    float ex = __expf(e - m);
    a->al[tid] = ex;
    float ssum = ex;
#pragma unroll
    for (int o = 16; o > 0; o >>= 1) ssum += __shfl_xor_sync(0xffffffffu, ssum, o);
    if (lane == 0) a->red[wid] = ssum;
    __syncthreads();
    if (tid == 0) {
        float s = 0.f;
        for (int i = 0; i < 16; ++i) s += a->red[i];
        a->red[17] = 1.f / s;
    }
    __syncthreads();
    float inv = a->red[17];

    // ctx: 4 tt-groups x 128 threads, float4 dims, smem combine
    {
        int tg = tid >> 7, li = tid & 127;
        int d0 = li * 4;
        const float* hb = h + (size_t)b * T * H2D;
        float sx = 0.f, sy = 0.f, sz = 0.f, sw = 0.f;
#pragma unroll 4
        for (int tt = tg * 128; tt < tg * 128 + 128; ++tt) {
            float av = a->al[tt];
            float4 v = *(const float4*)&hb[(size_t)tt * 512 + d0];
            sx = fmaf(av, v.x, sx);
            sy = fmaf(av, v.y, sy);
            sz = fmaf(av, v.z, sz);
            sw = fmaf(av, v.w, sw);
        }
        *(float4*)&a->part[tg][d0] = make_float4(sx, sy, sz, sw);
    }
    __syncthreads();
    {
        float cv = (a->part[0][tid] + a->part[1][tid] + a->part[2][tid] + a->part[3][tid]) * inv;
        a->vec[S + tid] = cv;
        g_ctx[b * H2D + tid] = cv;
    }
    __syncthreads();

    // out = Wcd @ [h2; ctx] + bcd
#pragma unroll
    for (int i = 0; i < 4; ++i) {
        int c = wid * 4 + i;
        const float* wr = Wcd + c * (S + H2D);
        float sum = 0.f;
#pragma unroll
        for (int idx = lane * 4; idx < S + H2D; idx += 128) {
            float4 w4 = *(const float4*)&wr[idx];
            float4 v4 = *(const float4*)&a->vec[idx];
            sum = fmaf(w4.x, v4.x, sum);
            sum = fmaf(w4.y, v4.y, sum);
            sum = fmaf(w4.z, v4.z, sum);
            sum = fmaf(w4.w, v4.w, sum);
        }
#pragma unroll
        for (int o = 16; o > 0; o >>= 1) sum += __shfl_xor_sync(0xffffffffu, sum, o);
        if (lane == 0) out[((size_t)b * NSTEP + t) * NCLS + c] = sum + bcd[c];
    }
    __syncthreads();
}

// ---------------- psi_h precompute ----------------
__global__ void k_psi(const float* __restrict__ h,
                      const float* __restrict__ Wpsi,
                      const float* __restrict__ bpsi)
{
    __shared__ __align__(16) float hs[32][36];
    __shared__ __align__(16) float ws[128][36];
    int b   = blockIdx.y;
    int t0  = blockIdx.x * 32;
    int tid = threadIdx.x;
    int tg  = tid & 7;
    int ag  = tid >> 3;

    float acc[16];
#pragma unroll
    for (int i = 0; i < 16; ++i) acc[i] = 0.f;

    for (int dc = 0; dc < H2D; dc += 32) {
#pragma unroll
        for (int i = 0; i < 4; ++i) {
            int lin = tid + i * 256;
            int r = lin >> 5, c = lin & 31;
            hs[r][c] = h[((size_t)b * T + t0 + r) * H2D + dc + c];
        }
#pragma unroll
        for (int i = 0; i < 16; ++i) {
            int lin = tid + i * 256;
            int r = lin >> 5, c = lin & 31;
            ws[r][c] = Wpsi[r * H2D + dc + c];
        }
        __syncthreads();
#pragma unroll
        for (int k = 0; k < 32; k += 4) {
            float4 hv[4], wv[4];
#pragma unroll
            for (int j = 0; j < 4; ++j) hv[j] = *(const float4*)&hs[tg * 4 + j][k];
#pragma unroll
            for (int j = 0; j < 4; ++j) wv[j] = *(const float4*)&ws[ag * 4 + j][k];
#pragma unroll
            for (int i = 0; i < 4; ++i)
#pragma unroll
                for (int j = 0; j < 4; ++j) {
                    acc[i * 4 + j] = fmaf(hv[i].x, wv[j].x, acc[i * 4 + j]);
                    acc[i * 4 + j] = fmaf(hv[i].y, wv[j].y, acc[i * 4 + j]);
                    acc[i * 4 + j] = fmaf(hv[i].z, wv[j].z, acc[i * 4 + j]);
                    acc[i * 4 + j] = fmaf(hv[i].w, wv[j].w, acc[i * 4 + j]);
                }
        }
        __syncthreads();
    }
#pragma unroll
    for (int i = 0; i < 4; ++i)
#pragma unroll
        for (int j = 0; j < 4; ++j) {
            int tt = t0 + tg * 4 + i;
            int a  = ag * 4 + j;
            g_psi[((size_t)b * T + tt) * ATT + a] = acc[i * 4 + j] + bpsi[a];
        }
}

// ---------------- persistent mega kernel ----------------
__global__ void __launch_bounds__(NTH, 1) k_mega(
        const int* __restrict__ x, const float* __restrict__ h,
        const float* __restrict__ Wih0, const float* __restrict__ Whh0,
        const float* __restrict__ bih0, const float* __restrict__ bhh0,
        const float* __restrict__ Wih1, const float* __restrict__ Whh1,
        const float* __restrict__ bih1, const float* __restrict__ bhh1,
        const float* __restrict__ Wphi, const float* __restrict__ bphi,
        const float* __restrict__ Wcd,  const float* __restrict__ bcd,
        float* __restrict__ out)
{
    extern __shared__ char smraw[];
    SmAll* sm = (SmAll*)smraw;

    int cta = blockIdx.x;
    int tid = threadIdx.x;
    int rg = cta >> 5, sp = cta & 31;
    unsigned phase = 0;
    if (tid == 0) phase = g_epoch;

    // one-time: stage persistent weight slices into smem [k][row]
    if (cta < 128) {
#pragma unroll 4
        for (int i = 0; i < 32; ++i) {
            int grow = rg * 512 + tid;
            float v0, v1;
            if (sp < 16) {
                v0 = Wih0[(size_t)grow * 576 + 64 + sp * 32 + i];
                v1 = Wih1[(size_t)grow * 512 + sp * 32 + i];
            } else {
                v0 = Whh0[(size_t)grow * 512 + (sp - 16) * 32 + i];
                v1 = Whh1[(size_t)grow * 512 + (sp - 16) * 32 + i];
            }
            sm->A0[i * 512 + tid] = v0;
            sm->A1[i * 512 + tid] = v1;
        }
    }

    // init states + ctx = h[:,0,:]
    if (cta < B) {
        int b = cta;
        g_ctx[b * S + tid]   = h[(size_t)b * T * H2D + tid];
        g_h1[0][b * S + tid] = 0.f;
        g_h2[0][b * S + tid] = 0.f;
        g_c1[b * S + tid]    = 0.f;
        g_c2[b * S + tid]    = 0.f;
    }
    gbar(phase, cta);

    for (int t = 0; t < NSTEP; ++t) {
        int par = t & 1;

        // Phase A: LSTM0 partial GEMMs
        if (cta < 128) {
            const float* z = (sp < 16) ? g_ctx : g_h1[par];
            lstm_gemm_phase(sm, sm->A0, tid, rg, sp, z, (sp & 15) * 32);
        }
        gbar(phase, cta);

        // Phase B: LSTM0 epilogue
        lstm_epi(cta, tid, Wih0, 576, bih0, bhh0, g_c1, g_h1[par ^ 1], x, t, 1);
        gbar(phase, cta);

        // Phase C: LSTM1 partial GEMMs
        if (cta < 128) {
            const float* z = (sp < 16) ? g_h1[par ^ 1] : g_h2[par];
            lstm_gemm_phase(sm, sm->A1, tid, rg, sp, z, (sp & 15) * 32);
        }
        gbar(phase, cta);

        // Phase D: LSTM1 epilogue
        lstm_epi(cta, tid, Wih1, 512, bih1, bhh1, g_c2, g_h2[par ^ 1], x, t, 0);
        gbar(phase, cta);

        // Phase E: attention + projection
        attn_phase(&sm->u.a, cta, tid, h, Wphi, bphi, Wcd, bcd,
                   g_h2[par ^ 1], out, t);
        gbar(phase, cta);
    }
}

// ---------------- launcher ----------------
extern "C" void kernel_launch(void* const* d_in, const int* in_sizes, int n_in,
                              void* d_out, int out_size)
{
    const int*   x    = (const int*)d_in[0];
    const float* h    = (const float*)d_in[1];
    const float* Wih0 = (const float*)d_in[2];
    const float* Whh0 = (const float*)d_in[3];
    const float* bih0 = (const float*)d_in[4];
    const float* bhh0 = (const float*)d_in[5];
    const float* Wih1 = (const float*)d_in[6];
    const float* Whh1 = (const float*)d_in[7];
    const float* bih1 = (const float*)d_in[8];
    const float* bhh1 = (const float*)d_in[9];
    const float* Wphi = (const float*)d_in[10];
    const float* bphi = (const float*)d_in[11];
    const float* Wpsi = (const float*)d_in[12];
    const float* bpsi = (const float*)d_in[13];
    const float* Wcd  = (const float*)d_in[14];
    const float* bcd  = (const float*)d_in[15];
    float* out = (float*)d_out;

    static int smem_set = 0;
    if (!smem_set) {
        cudaFuncSetAttribute(k_mega, cudaFuncAttributeMaxDynamicSharedMemorySize,
                             (int)sizeof(SmAll));
        smem_set = 1;
    }

    k_psi<<<dim3(T / 32, B), 256>>>(h, Wpsi, bpsi);
    k_mega<<<GRID, NTH, sizeof(SmAll)>>>(x, h, Wih0, Whh0, bih0, bhh0,
                                         Wih1, Whh1, bih1, bhh1,
                                         Wphi, bphi, Wcd, bcd, out);
}

// round 7
// speedup vs baseline: 2.0082x; 1.2833x over previous
#include <cuda_runtime.h>
#include <math.h>

#define B     64
#define T     512
#define NSTEP 128
#define S     512
#define H2D   512
#define ATT   128
#define NCLS  64
#define GRID  148
#define NTH   512

typedef unsigned long long ull;

// ---------------- scratch (static device globals; no allocation) ----------------
__device__ float g_psi[B * T * ATT];        // TRANSPOSED: [b][a][tt]
__device__ float g_part[8 * 64 * 2048];     // [(sp*64+b)*2048 + row]  (4.2 MB)
__device__ float g_h1[B * S];
__device__ float g_h2[B * S];
__device__ float g_c1[B * S];
__device__ float g_c2[B * S];
__device__ float g_ctx[B * H2D];
__device__ unsigned g_cnt1[8];
__device__ unsigned g_cnt2;
__device__ volatile unsigned g_epoch;

__device__ __forceinline__ float tanh_fast(float v)
{
    float r;
    asm("tanh.approx.f32 %0, %1;" : "=f"(r) : "f"(v));
    return r;
}
__device__ __forceinline__ float sigf(float v) { return 0.5f * tanh_fast(0.5f * v) + 0.5f; }

__device__ __forceinline__ ull fma2(ull a, ull b, ull c)
{
    ull d;
    asm("fma.rn.f32x2 %0, %1, %2, %3;" : "=l"(d) : "l"(a), "l"(b), "l"(c));
    return d;
}
__device__ __forceinline__ ull dup2(float a)
{
    ull d;
    asm("mov.b64 %0, {%1, %1};" : "=l"(d) : "f"(a));
    return d;
}
__device__ __forceinline__ float pick(ull u, int hi)
{
    float2 f = *(float2*)&u;
    return hi ? f.y : f.x;
}

// -------- two-level grid barrier (148 co-resident CTAs) ------------------------
__device__ __forceinline__ void gbar(unsigned& phase, int cta)
{
    __syncthreads();
    if (threadIdx.x == 0) {
        ++phase;
        __threadfence();
        int grp = cta & 7;
        unsigned gsz = 18u + (grp < 4 ? 1u : 0u);   // 148 = 4*19 + 4*18
        if (atomicAdd(&g_cnt1[grp], 1u) == gsz - 1u) {
            g_cnt1[grp] = 0u;
            __threadfence();
            if (atomicAdd(&g_cnt2, 1u) == 7u) {
                g_cnt2 = 0u;
                __threadfence();
                g_epoch = phase;
            } else {
                while (g_epoch != phase) {}
            }
        } else {
            while (g_epoch != phase) {}
        }
        __threadfence();
    }
    __syncthreads();
}

// ---------------- smem ----------------
struct SmAttn {
    __align__(16) float part[16][520];      // 33.3 KB (e partials use rows 0..3)
    __align__(16) float vec[1024];          // [h2 ; ctx]
    __align__(16) float phi[ATT];
    __align__(16) float al[T];
    __align__(16) float red[40];
};
struct SmAll {
    float A0[128 * 128];                    // 64 KB persistent LSTM0 slice [k][row]
    float A1[128 * 128];                    // 64 KB persistent LSTM1 slice
    union { float Bs[128 * 72]; SmAttn a; } u;
};

// -------- GEMM: 128 gate rows x 64 batches x K=128; thread tile 4r x 4b ---------
__device__ __forceinline__ void lstm_gemm(const float* __restrict__ As,
        float* __restrict__ Bs, int tid, int rg, int sp,
        const float* __restrict__ z, int koff)
{
    // stage B [k][b] (coalesced LDG: lanes sweep k)
#pragma unroll
    for (int i = 0; i < 16; ++i) {
        int idx = i * 512 + tid;
        int k = idx & 127, b = idx >> 7;
        Bs[k * 72 + b] = z[b * 512 + koff + k];
    }
    __syncthreads();

    int rt = tid >> 4;          // rows rt*4..+3
    int bt = tid & 15;          // batches bt*4..+3 (2 fma2 pairs)
    const float* Ab = As + rt * 4;

    ull acc[4][2];
#pragma unroll
    for (int i = 0; i < 4; ++i) { acc[i][0] = 0ull; acc[i][1] = 0ull; }

#pragma unroll 8
    for (int k = 0; k < 128; ++k) {
        float4 a = *(const float4*)&Ab[k * 128];
        ulonglong2 bv = *(const ulonglong2*)&Bs[k * 72 + bt * 4];
        ull d;
        d = dup2(a.x); acc[0][0] = fma2(d, bv.x, acc[0][0]); acc[0][1] = fma2(d, bv.y, acc[0][1]);
        d = dup2(a.y); acc[1][0] = fma2(d, bv.x, acc[1][0]); acc[1][1] = fma2(d, bv.y, acc[1][1]);
        d = dup2(a.z); acc[2][0] = fma2(d, bv.x, acc[2][0]); acc[2][1] = fma2(d, bv.y, acc[2][1]);
        d = dup2(a.w); acc[3][0] = fma2(d, bv.x, acc[3][0]); acc[3][1] = fma2(d, bv.y, acc[3][1]);
    }

    int row0 = rg * 128 + rt * 4;
#pragma unroll
    for (int j = 0; j < 4; ++j) {
        int b = bt * 4 + j;
        int p = j >> 1, hi = j & 1;
        float4 v = make_float4(pick(acc[0][p], hi), pick(acc[1][p], hi),
                               pick(acc[2][p], hi), pick(acc[3][p], hi));
        *(float4*)&g_part[(size_t)(sp * 64 + b) * 2048 + row0] = v;
    }
    __syncthreads();
}

// -------- LSTM0 epilogue: CTA = batch, thread = unit (fully coalesced) ----------
__device__ __forceinline__ void epi0(int cta, int tid,
        const float* __restrict__ Wih0,
        const float* __restrict__ bih, const float* __restrict__ bhh,
        const int* __restrict__ x, int t)
{
    if (cta >= B) return;
    int b = cta, u = tid;
    float pre[4];
#pragma unroll
    for (int g = 0; g < 4; ++g) {
        int row = g * 512 + u;
        float s = bih[row] + bhh[row];
#pragma unroll
        for (int sp = 0; sp < 8; ++sp)
            s += g_part[(size_t)(sp * 64 + b) * 2048 + row];
        pre[g] = s;
    }
    int cls = x[b * NSTEP + t];
#pragma unroll
    for (int g = 0; g < 4; ++g)
        pre[g] += Wih0[(size_t)(g * 512 + u) * 576 + cls];
    float co = g_c1[b * S + u];
    float cn = sigf(pre[1]) * co + sigf(pre[0]) * tanh_fast(pre[2]);
    float hn = sigf(pre[3]) * tanh_fast(cn);
    g_c1[b * S + u] = cn;
    g_h1[b * S + u] = hn;
}

// -------- fused LSTM1-epilogue + attention + projection, CTA = batch ------------
__device__ __forceinline__ void attn_phase(SmAttn* a, int cta, int tid,
        const float* __restrict__ h,
        const float* __restrict__ bih1, const float* __restrict__ bhh1,
        const float* __restrict__ Wphi, const float* __restrict__ bphi,
        const float* __restrict__ Wcd,  const float* __restrict__ bcd,
        float* __restrict__ out, int t)
{
    if (cta >= B) return;
    int b    = cta;
    int wid  = tid >> 5;
    int lane = tid & 31;

    // ---- LSTM1 epilogue (u = tid) ----
    {
        int u = tid;
        float pre[4];
#pragma unroll
        for (int g = 0; g < 4; ++g) {
            int row = g * 512 + u;
            float s = bih1[row] + bhh1[row];
#pragma unroll
            for (int sp = 0; sp < 8; ++sp)
                s += g_part[(size_t)(sp * 64 + b) * 2048 + row];
            pre[g] = s;
        }
        float co = g_c2[b * S + u];
        float cn = sigf(pre[1]) * co + sigf(pre[0]) * tanh_fast(pre[2]);
        float hn = sigf(pre[3]) * tanh_fast(cn);
        g_c2[b * S + u] = cn;
        g_h2[b * S + u] = hn;
        a->vec[u] = hn;
    }
    __syncthreads();

    // ---- phi = Wphi @ h2 + bphi (16 warps x 8 rows) ----
#pragma unroll
    for (int i = 0; i < 8; ++i) {
        int aa = wid * 8 + i;
        const float* wr = Wphi + aa * S;
        float sum = 0.f;
#pragma unroll
        for (int idx = lane * 4; idx < S; idx += 128) {
            float4 w4 = *(const float4*)&wr[idx];
            float4 v4 = *(const float4*)&a->vec[idx];
            sum = fmaf(w4.x, v4.x, sum);
            sum = fmaf(w4.y, v4.y, sum);
            sum = fmaf(w4.z, v4.z, sum);
            sum = fmaf(w4.w, v4.w, sum);
        }
#pragma unroll
        for (int o = 16; o > 0; o >>= 1) sum += __shfl_xor_sync(0xffffffffu, sum, o);
        if (lane == 0) a->phi[aa] = sum + bphi[aa];
    }
    __syncthreads();

    // ---- e[tt] via TRANSPOSED psi [b][a][tt]: coalesced, no shfl ----
    {
        int aw = tid >> 7;           // a-group 0..3 (32 a's each)
        int q  = tid & 127;          // tt quad q*4..+3
        const float* pb = g_psi + ((size_t)b * ATT + aw * 32) * T + q * 4;
        float4 acc = make_float4(0.f, 0.f, 0.f, 0.f);
#pragma unroll 8
        for (int ai = 0; ai < 32; ++ai) {
            float pa = a->phi[aw * 32 + ai];
            float4 v = *(const float4*)&pb[(size_t)ai * T];
            acc.x = fmaf(pa, v.x, acc.x);
            acc.y = fmaf(pa, v.y, acc.y);
            acc.z = fmaf(pa, v.z, acc.z);
            acc.w = fmaf(pa, v.w, acc.w);
        }
        *(float4*)&a->part[aw][q * 4] = acc;
    }
    __syncthreads();

    // ---- combine e + softmax (one value per thread) ----
    float e = a->part[0][tid] + a->part[1][tid] + a->part[2][tid] + a->part[3][tid];
    float m = e;
#pragma unroll
    for (int o = 16; o > 0; o >>= 1) m = fmaxf(m, __shfl_xor_sync(0xffffffffu, m, o));
    if (lane == 0) a->red[wid] = m;
    __syncthreads();
    if (tid == 0) {
        float mm = a->red[0];
        for (int i = 1; i < 16; ++i) mm = fmaxf(mm, a->red[i]);
        a->red[16] = mm;
    }
    __syncthreads();
    m = a->red[16];
    float ex = __expf(e - m);
    a->al[tid] = ex;
    float ssum = ex;
#pragma unroll
    for (int o = 16; o > 0; o >>= 1) ssum += __shfl_xor_sync(0xffffffffu, ssum, o);
    if (lane == 0) a->red[wid] = ssum;
    __syncthreads();
    if (tid == 0) {
        float s = 0.f;
        for (int i = 0; i < 16; ++i) s += a->red[i];
        a->red[17] = 1.f / s;
    }
    __syncthreads();
    float inv = a->red[17];

    // ---- ctx: 16 warps over tt-groups, fully coalesced float4 over dims --------
    {
        const float* hb = h + (size_t)b * T * H2D;
        float4 c0 = make_float4(0.f, 0.f, 0.f, 0.f);
        float4 c1 = c0, c2 = c0, c3 = c0;
#pragma unroll 4
        for (int tt = wid * 32; tt < wid * 32 + 32; ++tt) {
            float av = a->al[tt];
            const float* hr = hb + (size_t)tt * H2D + lane * 4;
            float4 v0 = *(const float4*)&hr[0];
            float4 v1 = *(const float4*)&hr[128];
            float4 v2 = *(const float4*)&hr[256];
            float4 v3 = *(const float4*)&hr[384];
            c0.x = fmaf(av, v0.x, c0.x); c0.y = fmaf(av, v0.y, c0.y);
            c0.z = fmaf(av, v0.z, c0.z); c0.w = fmaf(av, v0.w, c0.w);
            c1.x = fmaf(av, v1.x, c1.x); c1.y = fmaf(av, v1.y, c1.y);
            c1.z = fmaf(av, v1.z, c1.z); c1.w = fmaf(av, v1.w, c1.w);
            c2.x = fmaf(av, v2.x, c2.x); c2.y = fmaf(av, v2.y, c2.y);
            c2.z = fmaf(av, v2.z, c2.z); c2.w = fmaf(av, v2.w, c2.w);
            c3.x = fmaf(av, v3.x, c3.x); c3.y = fmaf(av, v3.y, c3.y);
            c3.z = fmaf(av, v3.z, c3.z); c3.w = fmaf(av, v3.w, c3.w);
        }
        *(float4*)&a->part[wid][lane * 4]       = c0;
        *(float4*)&a->part[wid][128 + lane * 4] = c1;
        *(float4*)&a->part[wid][256 + lane * 4] = c2;
        *(float4*)&a->part[wid][384 + lane * 4] = c3;
    }
    __syncthreads();
    {
        float cv = 0.f;
#pragma unroll
        for (int w = 0; w < 16; ++w) cv += a->part[w][tid];
        cv *= inv;
        a->vec[S + tid] = cv;
        g_ctx[b * H2D + tid] = cv;
    }
    __syncthreads();

    // ---- out = Wcd @ [h2; ctx] + bcd (16 warps x 4 classes) ----
#pragma unroll
    for (int i = 0; i < 4; ++i) {
        int c = wid * 4 + i;
        const float* wr = Wcd + c * (S + H2D);
        float sum = 0.f;
#pragma unroll
        for (int idx = lane * 4; idx < S + H2D; idx += 128) {
            float4 w4 = *(const float4*)&wr[idx];
            float4 v4 = *(const float4*)&a->vec[idx];
            sum = fmaf(w4.x, v4.x, sum);
            sum = fmaf(w4.y, v4.y, sum);
            sum = fmaf(w4.z, v4.z, sum);
            sum = fmaf(w4.w, v4.w, sum);
        }
#pragma unroll
        for (int o = 16; o > 0; o >>= 1) sum += __shfl_xor_sync(0xffffffffu, sum, o);
        if (lane == 0) out[((size_t)b * NSTEP + t) * NCLS + c] = sum + bcd[c];
    }
    __syncthreads();
}

// ---------------- psi_h precompute (TRANSPOSED output [b][a][tt]) ---------------
__global__ void k_psi(const float* __restrict__ h,
                      const float* __restrict__ Wpsi,
                      const float* __restrict__ bpsi)
{
    __shared__ __align__(16) float hs[32][36];
    __shared__ __align__(16) float ws[128][36];
    int b   = blockIdx.y;
    int t0  = blockIdx.x * 32;
    int tid = threadIdx.x;
    int tg  = tid & 7;
    int ag  = tid >> 3;

    float acc[16];
#pragma unroll
    for (int i = 0; i < 16; ++i) acc[i] = 0.f;

    for (int dc = 0; dc < H2D; dc += 32) {
#pragma unroll
        for (int i = 0; i < 4; ++i) {
            int lin = tid + i * 256;
            int r = lin >> 5, c = lin & 31;
            hs[r][c] = h[((size_t)b * T + t0 + r) * H2D + dc + c];
        }
#pragma unroll
        for (int i = 0; i < 16; ++i) {
            int lin = tid + i * 256;
            int r = lin >> 5, c = lin & 31;
            ws[r][c] = Wpsi[r * H2D + dc + c];
        }
        __syncthreads();
#pragma unroll
        for (int k = 0; k < 32; k += 4) {
            float4 hv[4], wv[4];
#pragma unroll
            for (int j = 0; j < 4; ++j) hv[j] = *(const float4*)&hs[tg * 4 + j][k];
#pragma unroll
            for (int j = 0; j < 4; ++j) wv[j] = *(const float4*)&ws[ag * 4 + j][k];
#pragma unroll
            for (int i = 0; i < 4; ++i)
#pragma unroll
                for (int j = 0; j < 4; ++j) {
                    acc[i * 4 + j] = fmaf(hv[i].x, wv[j].x, acc[i * 4 + j]);
                    acc[i * 4 + j] = fmaf(hv[i].y, wv[j].y, acc[i * 4 + j]);
                    acc[i * 4 + j] = fmaf(hv[i].z, wv[j].z, acc[i * 4 + j]);
                    acc[i * 4 + j] = fmaf(hv[i].w, wv[j].w, acc[i * 4 + j]);
                }
        }
        __syncthreads();
    }
#pragma unroll
    for (int i = 0; i < 4; ++i)
#pragma unroll
        for (int j = 0; j < 4; ++j) {
            int tt = t0 + tg * 4 + i;
            int aa = ag * 4 + j;
            g_psi[((size_t)b * ATT + aa) * T + tt] = acc[i * 4 + j] + bpsi[aa];
        }
}

// ---------------- persistent mega kernel ----------------
__global__ void __launch_bounds__(NTH, 1) k_mega(
        const int* __restrict__ x, const float* __restrict__ h,
        const float* __restrict__ Wih0, const float* __restrict__ Whh0,
        const float* __restrict__ bih0, const float* __restrict__ bhh0,
        const float* __restrict__ Wih1, const float* __restrict__ Whh1,
        const float* __restrict__ bih1, const float* __restrict__ bhh1,
        const float* __restrict__ Wphi, const float* __restrict__ bphi,
        const float* __restrict__ Wcd,  const float* __restrict__ bcd,
        float* __restrict__ out)
{
    extern __shared__ char smraw[];
    SmAll* sm = (SmAll*)smraw;

    int cta = blockIdx.x;
    int tid = threadIdx.x;
    int rg = cta >> 3, sp = cta & 7;      // 16 row-groups x 8 K-splits
    unsigned phase = 0;
    if (tid == 0) phase = g_epoch;

    // one-time: stage persistent weight slices [k][row]
    if (cta < 128) {
#pragma unroll 4
        for (int i = 0; i < 32; ++i) {
            int idx = i * 512 + tid;
            int k = idx & 127, r = idx >> 7;
            int grow = rg * 128 + r;
            float v0, v1;
            if (sp < 4) {
                v0 = Wih0[(size_t)grow * 576 + 64 + sp * 128 + k];
                v1 = Wih1[(size_t)grow * 512 + sp * 128 + k];
            } else {
                v0 = Whh0[(size_t)grow * 512 + (sp - 4) * 128 + k];
                v1 = Whh1[(size_t)grow * 512 + (sp - 4) * 128 + k];
            }
            sm->A0[k * 128 + r] = v0;
            sm->A1[k * 128 + r] = v1;
        }
    }

    // init states + ctx = h[:,0,:]
    if (cta < B) {
        int b = cta;
        g_ctx[b * S + tid] = h[(size_t)b * T * H2D + tid];
        g_h1[b * S + tid]  = 0.f;
        g_h2[b * S + tid]  = 0.f;
        g_c1[b * S + tid]  = 0.f;
        g_c2[b * S + tid]  = 0.f;
    }
    gbar(phase, cta);

    for (int t = 0; t < NSTEP; ++t) {
        // P1: LSTM0 GEMM (ih on ctx[t-1], hh on h1[t-1])
        if (cta < 128) {
            const float* z = (sp < 4) ? g_ctx : g_h1;
            lstm_gemm(sm->A0, sm->u.Bs, tid, rg, sp, z, (sp & 3) * 128);
        }
        gbar(phase, cta);

        // P2: LSTM0 epilogue -> h1[t]
        epi0(cta, tid, Wih0, bih0, bhh0, x, t);
        gbar(phase, cta);

        // P3: LSTM1 GEMM (ih on h1[t], hh on h2[t-1])
        if (cta < 128) {
            const float* z = (sp < 4) ? g_h1 : g_h2;
            lstm_gemm(sm->A1, sm->u.Bs, tid, rg, sp, z, (sp & 3) * 128);
        }
        gbar(phase, cta);

        // P4: LSTM1 epilogue + attention + projection -> h2[t], ctx[t], out[t]
        attn_phase(&sm->u.a, cta, tid, h, bih1, bhh1, Wphi, bphi, Wcd, bcd, out, t);
        gbar(phase, cta);
    }
}

// ---------------- launcher ----------------
extern "C" void kernel_launch(void* const* d_in, const int* in_sizes, int n_in,
                              void* d_out, int out_size)
{
    const int*   x    = (const int*)d_in[0];
    const float* h    = (const float*)d_in[1];
    const float* Wih0 = (const float*)d_in[2];
    const float* Whh0 = (const float*)d_in[3];
    const float* bih0 = (const float*)d_in[4];
    const float* bhh0 = (const float*)d_in[5];
    const float* Wih1 = (const float*)d_in[6];
    const float* Whh1 = (const float*)d_in[7];
    const float* bih1 = (const float*)d_in[8];
    const float* bhh1 = (const float*)d_in[9];
    const float* Wphi = (const float*)d_in[10];
    const float* bphi = (const float*)d_in[11];
    const float* Wpsi = (const float*)d_in[12];
    const float* bpsi = (const float*)d_in[13];
    const float* Wcd  = (const float*)d_in[14];
    const float* bcd  = (const float*)d_in[15];
    float* out = (float*)d_out;

    static int smem_set = 0;
    if (!smem_set) {
        cudaFuncSetAttribute(k_mega, cudaFuncAttributeMaxDynamicSharedMemorySize,
                             (int)sizeof(SmAll));
        smem_set = 1;
    }

    k_psi<<<dim3(T / 32, B), 256>>>(h, Wpsi, bpsi);
    k_mega<<<GRID, NTH, sizeof(SmAll)>>>(x, h, Wih0, Whh0, bih0, bhh0,
                                         Wih1, Whh1, bih1, bhh1,
                                         Wphi, bphi, Wcd, bcd, out);
}

// round 8
// speedup vs baseline: 2.3780x; 1.1841x over previous
#include <cuda_runtime.h>
#include <cuda_fp16.h>
#include <math.h>

#define B     64
#define T     512
#define NSTEP 128
#define S     512
#define H2D   512
#define ATT   128
#define NCLS  64
#define GRID  148
#define NTH   512

typedef unsigned long long ull;

// ---------------- scratch (static device globals; no allocation) ----------------
__device__ float  g_psi[B * T * ATT];        // TRANSPOSED: [b][a][tt]
__device__ __half g_h16[B * T * H2D];        // fp16 copy of h for ctx reduction
__device__ float  g_part[20 * 64 * 2048];    // [(slot*64+b)*2048 + row]  (10.5 MB)
__device__ float  g_h1[B * S];
__device__ float  g_h2[B * S];
__device__ float  g_c1[B * S];
__device__ float  g_c2[B * S];
__device__ float  g_ctx[B * H2D];
__device__ unsigned g_cnt1[8];
__device__ unsigned g_cnt2;
__device__ volatile unsigned g_epoch;

__device__ __forceinline__ float tanh_fast(float v)
{
    float r;
    asm("tanh.approx.f32 %0, %1;" : "=f"(r) : "f"(v));
    return r;
}
__device__ __forceinline__ float sigf(float v) { return 0.5f * tanh_fast(0.5f * v) + 0.5f; }

__device__ __forceinline__ ull fma2(ull a, ull b, ull c)
{
    ull d;
    asm("fma.rn.f32x2 %0, %1, %2, %3;" : "=l"(d) : "l"(a), "l"(b), "l"(c));
    return d;
}
__device__ __forceinline__ ull dup2(float a)
{
    ull d;
    asm("mov.b64 %0, {%1, %1};" : "=l"(d) : "f"(a));
    return d;
}
__device__ __forceinline__ float pick(ull u, int hi)
{
    float2 f = *(float2*)&u;
    return hi ? f.y : f.x;
}

// -------- two-level grid barrier (148 co-resident CTAs) ------------------------
__device__ __forceinline__ void gbar(unsigned& phase, int cta)
{
    __syncthreads();
    if (threadIdx.x == 0) {
        ++phase;
        __threadfence();
        int grp = cta & 7;
        unsigned gsz = 18u + (grp < 4 ? 1u : 0u);   // 148 = 4*19 + 4*18
        if (atomicAdd(&g_cnt1[grp], 1u) == gsz - 1u) {
            g_cnt1[grp] = 0u;
            __threadfence();
            if (atomicAdd(&g_cnt2, 1u) == 7u) {
                g_cnt2 = 0u;
                __threadfence();
                g_epoch = phase;
            } else {
                while (g_epoch != phase) {}
            }
        } else {
            while (g_epoch != phase) {}
        }
        __threadfence();
    }
    __syncthreads();
}

// ---------------- smem ----------------
struct SmAttn {
    __align__(16) float part[16][520];
    __align__(16) float vec[1024];
    __align__(16) float phi[ATT];
    __align__(16) float al[T];
    __align__(16) float red[40];
};
struct SmAll {
    float Wa[128 * 128];    // cta<64: Wih0 slice (J1) | cta 64-127: Whh0 slice (J2)
    float Wb[128 * 128];    // cta 64-127: Whh1 slice (J4)
    float Wc[64 * 128];     // all 128: Wih1 slice (J3, K=64)
    union { __align__(16) float Bs[128 * 72]; SmAttn a; } u;
};

// -------- GEMM: 128 gate rows x 64 batches x K=KT; thread tile 4r x 4b ----------
template<int KT>
__device__ __forceinline__ void lstm_gemm(const float* __restrict__ As,
        float* __restrict__ Bs, int tid, int rowBase, int slot,
        const float* __restrict__ z, int koff)
{
#pragma unroll
    for (int i = 0; i < (KT * 64) / 512; ++i) {
        int idx = i * 512 + tid;
        int k = idx % KT, b = idx / KT;
        Bs[k * 72 + b] = z[b * 512 + koff + k];
    }
    __syncthreads();

    int rt = tid >> 4;          // rows rt*4..+3
    int bt = tid & 15;          // batches bt*4..+3
    const float* Ab = As + rt * 4;

    ull acc[4][2];
#pragma unroll
    for (int i = 0; i < 4; ++i) { acc[i][0] = 0ull; acc[i][1] = 0ull; }

#pragma unroll 8
    for (int k = 0; k < KT; ++k) {
        float4 a = *(const float4*)&Ab[k * 128];
        ulonglong2 bv = *(const ulonglong2*)&Bs[k * 72 + bt * 4];
        ull d;
        d = dup2(a.x); acc[0][0] = fma2(d, bv.x, acc[0][0]); acc[0][1] = fma2(d, bv.y, acc[0][1]);
        d = dup2(a.y); acc[1][0] = fma2(d, bv.x, acc[1][0]); acc[1][1] = fma2(d, bv.y, acc[1][1]);
        d = dup2(a.z); acc[2][0] = fma2(d, bv.x, acc[2][0]); acc[2][1] = fma2(d, bv.y, acc[2][1]);
        d = dup2(a.w); acc[3][0] = fma2(d, bv.x, acc[3][0]); acc[3][1] = fma2(d, bv.y, acc[3][1]);
    }

    int row0 = rowBase + rt * 4;
#pragma unroll
    for (int j = 0; j < 4; ++j) {
        int b = bt * 4 + j;
        int p = j >> 1, hi = j & 1;
        float4 v = make_float4(pick(acc[0][p], hi), pick(acc[1][p], hi),
                               pick(acc[2][p], hi), pick(acc[3][p], hi));
        *(float4*)&g_part[(size_t)(slot * 64 + b) * 2048 + row0] = v;
    }
}

// -------- LSTM0 epilogue: CTA = batch, thread = unit, sums slots 0-7 ------------
__device__ __forceinline__ void epi0(int cta, int tid,
        const float* __restrict__ Wih0,
        const float* __restrict__ bih, const float* __restrict__ bhh,
        const int* __restrict__ x, int t)
{
    if (cta >= B) return;
    int b = cta, u = tid;
    float pre[4];
#pragma unroll
    for (int g = 0; g < 4; ++g) {
        int row = g * 512 + u;
        float s = bih[row] + bhh[row];
#pragma unroll
        for (int sp = 0; sp < 8; ++sp)
            s += g_part[(size_t)(sp * 64 + b) * 2048 + row];
        pre[g] = s;
    }
    int cls = x[b * NSTEP + t];
#pragma unroll
    for (int g = 0; g < 4; ++g)
        pre[g] += Wih0[(size_t)(g * 512 + u) * 576 + cls];
    float co = g_c1[b * S + u];
    float cn = sigf(pre[1]) * co + sigf(pre[0]) * tanh_fast(pre[2]);
    float hn = sigf(pre[3]) * tanh_fast(cn);
    g_c1[b * S + u] = cn;
    g_h1[b * S + u] = hn;
}

// -------- fused LSTM1-epilogue (slots 8-19) + attention + projection ------------
__device__ __forceinline__ void attn_phase(SmAttn* a, int cta, int tid,
        const float* __restrict__ bih1, const float* __restrict__ bhh1,
        const float* __restrict__ Wphi, const float* __restrict__ bphi,
        const float* __restrict__ Wcd,  const float* __restrict__ bcd,
        float* __restrict__ out, int t)
{
    int b    = cta;
    int wid  = tid >> 5;
    int lane = tid & 31;

    // ---- LSTM1 epilogue ----
    {
        int u = tid;
        float pre[4];
#pragma unroll
        for (int g = 0; g < 4; ++g) {
            int row = g * 512 + u;
            float s = bih1[row] + bhh1[row];
#pragma unroll
            for (int sp = 8; sp < 20; ++sp)
                s += g_part[(size_t)(sp * 64 + b) * 2048 + row];
            pre[g] = s;
        }
        float co = g_c2[b * S + u];
        float cn = sigf(pre[1]) * co + sigf(pre[0]) * tanh_fast(pre[2]);
        float hn = sigf(pre[3]) * tanh_fast(cn);
        g_c2[b * S + u] = cn;
        g_h2[b * S + u] = hn;
        a->vec[u] = hn;
    }
    __syncthreads();

    // ---- phi = Wphi @ h2 + bphi ----
#pragma unroll
    for (int i = 0; i < 8; ++i) {
        int aa = wid * 8 + i;
        const float* wr = Wphi + aa * S;
        float sum = 0.f;
#pragma unroll
        for (int idx = lane * 4; idx < S; idx += 128) {
            float4 w4 = *(const float4*)&wr[idx];
            float4 v4 = *(const float4*)&a->vec[idx];
            sum = fmaf(w4.x, v4.x, sum);
            sum = fmaf(w4.y, v4.y, sum);
            sum = fmaf(w4.z, v4.z, sum);
            sum = fmaf(w4.w, v4.w, sum);
        }
#pragma unroll
        for (int o = 16; o > 0; o >>= 1) sum += __shfl_xor_sync(0xffffffffu, sum, o);
        if (lane == 0) a->phi[aa] = sum + bphi[aa];
    }
    __syncthreads();

    // ---- e[tt] via transposed psi [b][a][tt] (coalesced) ----
    {
        int aw = tid >> 7;
        int q  = tid & 127;
        const float* pb = g_psi + ((size_t)b * ATT + aw * 32) * T + q * 4;
        float4 acc = make_float4(0.f, 0.f, 0.f, 0.f);
#pragma unroll 8
        for (int ai = 0; ai < 32; ++ai) {
            float pa = a->phi[aw * 32 + ai];
            float4 v = *(const float4*)&pb[(size_t)ai * T];
            acc.x = fmaf(pa, v.x, acc.x);
            acc.y = fmaf(pa, v.y, acc.y);
            acc.z = fmaf(pa, v.z, acc.z);
            acc.w = fmaf(pa, v.w, acc.w);
        }
        *(float4*)&a->part[aw][q * 4] = acc;
    }
    __syncthreads();

    // ---- softmax ----
    float e = a->part[0][tid] + a->part[1][tid] + a->part[2][tid] + a->part[3][tid];
    float m = e;
#pragma unroll
    for (int o = 16; o > 0; o >>= 1) m = fmaxf(m, __shfl_xor_sync(0xffffffffu, m, o));
    if (lane == 0) a->red[wid] = m;
    __syncthreads();
    if (tid == 0) {
        float mm = a->red[0];
        for (int i = 1; i < 16; ++i) mm = fmaxf(mm, a->red[i]);
        a->red[16] = mm;
    }
    __syncthreads();
    m = a->red[16];
    float ex = __expf(e - m);
    a->al[tid] = ex;
    float ssum = ex;
#pragma unroll
    for (int o = 16; o > 0; o >>= 1) ssum += __shfl_xor_sync(0xffffffffu, ssum, o);
    if (lane == 0) a->red[wid] = ssum;
    __syncthreads();
    if (tid == 0) {
        float s = 0.f;
        for (int i = 0; i < 16; ++i) s += a->red[i];
        a->red[17] = 1.f / s;
    }
    __syncthreads();
    float inv = a->red[17];

    // ---- ctx via fp16 h: 16 warps over tt, each lane 16 dims (2x 8-half loads) --
    {
        const __half* hb = g_h16 + (size_t)b * T * H2D;
        float acc[16];
#pragma unroll
        for (int i = 0; i < 16; ++i) acc[i] = 0.f;
#pragma unroll 4
        for (int tt = wid * 32; tt < wid * 32 + 32; ++tt) {
            float av = a->al[tt];
            const __half* hr = hb + (size_t)tt * H2D + lane * 8;
            uint4 u0 = *(const uint4*)hr;
            uint4 u1 = *(const uint4*)(hr + 256);
            const __half2* p0 = (const __half2*)&u0;
            const __half2* p1 = (const __half2*)&u1;
#pragma unroll
            for (int j = 0; j < 4; ++j) {
                float2 f0 = __half22float2(p0[j]);
                float2 f1 = __half22float2(p1[j]);
                acc[j * 2 + 0] = fmaf(av, f0.x, acc[j * 2 + 0]);
                acc[j * 2 + 1] = fmaf(av, f0.y, acc[j * 2 + 1]);
                acc[8 + j * 2 + 0] = fmaf(av, f1.x, acc[8 + j * 2 + 0]);
                acc[8 + j * 2 + 1] = fmaf(av, f1.y, acc[8 + j * 2 + 1]);
            }
        }
#pragma unroll
        for (int j = 0; j < 2; ++j) {
            *(float4*)&a->part[wid][j * 256 + lane * 8]     =
                make_float4(acc[j * 8 + 0], acc[j * 8 + 1], acc[j * 8 + 2], acc[j * 8 + 3]);
            *(float4*)&a->part[wid][j * 256 + lane * 8 + 4] =
                make_float4(acc[j * 8 + 4], acc[j * 8 + 5], acc[j * 8 + 6], acc[j * 8 + 7]);
        }
    }
    __syncthreads();
    {
        float cv = 0.f;
#pragma unroll
        for (int w = 0; w < 16; ++w) cv += a->part[w][tid];
        cv *= inv;
        a->vec[S + tid] = cv;
        g_ctx[b * H2D + tid] = cv;
    }
    __syncthreads();

    // ---- out = Wcd @ [h2; ctx] + bcd ----
#pragma unroll
    for (int i = 0; i < 4; ++i) {
        int c = wid * 4 + i;
        const float* wr = Wcd + c * (S + H2D);
        float sum = 0.f;
#pragma unroll
        for (int idx = lane * 4; idx < S + H2D; idx += 128) {
            float4 w4 = *(const float4*)&wr[idx];
            float4 v4 = *(const float4*)&a->vec[idx];
            sum = fmaf(w4.x, v4.x, sum);
            sum = fmaf(w4.y, v4.y, sum);
            sum = fmaf(w4.z, v4.z, sum);
            sum = fmaf(w4.w, v4.w, sum);
        }
#pragma unroll
        for (int o = 16; o > 0; o >>= 1) sum += __shfl_xor_sync(0xffffffffu, sum, o);
        if (lane == 0) out[((size_t)b * NSTEP + t) * NCLS + c] = sum + bcd[c];
    }
    __syncthreads();
}

// ---------------- fp16 copy of h ----------------
__global__ void k_h16(const float* __restrict__ h)
{
    size_t i = ((size_t)blockIdx.x * 256 + threadIdx.x) * 8;
    float4 v0 = *(const float4*)&h[i];
    float4 v1 = *(const float4*)&h[i + 4];
    __half2 o[4];
    o[0] = __floats2half2_rn(v0.x, v0.y);
    o[1] = __floats2half2_rn(v0.z, v0.w);
    o[2] = __floats2half2_rn(v1.x, v1.y);
    o[3] = __floats2half2_rn(v1.z, v1.w);
    *(uint4*)&g_h16[i] = *(uint4*)o;
}

// ---------------- psi_h precompute (transposed output [b][a][tt]) ---------------
__global__ void k_psi(const float* __restrict__ h,
                      const float* __restrict__ Wpsi,
                      const float* __restrict__ bpsi)
{
    __shared__ __align__(16) float hs[32][36];
    __shared__ __align__(16) float ws[128][36];
    int b   = blockIdx.y;
    int t0  = blockIdx.x * 32;
    int tid = threadIdx.x;
    int tg  = tid & 7;
    int ag  = tid >> 3;

    float acc[16];
#pragma unroll
    for (int i = 0; i < 16; ++i) acc[i] = 0.f;

    for (int dc = 0; dc < H2D; dc += 32) {
#pragma unroll
        for (int i = 0; i < 4; ++i) {
            int lin = tid + i * 256;
            int r = lin >> 5, c = lin & 31;
            hs[r][c] = h[((size_t)b * T + t0 + r) * H2D + dc + c];
        }
#pragma unroll
        for (int i = 0; i < 16; ++i) {
            int lin = tid + i * 256;
            int r = lin >> 5, c = lin & 31;
            ws[r][c] = Wpsi[r * H2D + dc + c];
        }
        __syncthreads();
#pragma unroll
        for (int k = 0; k < 32; k += 4) {
            float4 hv[4], wv[4];
#pragma unroll
            for (int j = 0; j < 4; ++j) hv[j] = *(const float4*)&hs[tg * 4 + j][k];
#pragma unroll
            for (int j = 0; j < 4; ++j) wv[j] = *(const float4*)&ws[ag * 4 + j][k];
#pragma unroll
            for (int i = 0; i < 4; ++i)
#pragma unroll
                for (int j = 0; j < 4; ++j) {
                    acc[i * 4 + j] = fmaf(hv[i].x, wv[j].x, acc[i * 4 + j]);
                    acc[i * 4 + j] = fmaf(hv[i].y, wv[j].y, acc[i * 4 + j]);
                    acc[i * 4 + j] = fmaf(hv[i].z, wv[j].z, acc[i * 4 + j]);
                    acc[i * 4 + j] = fmaf(hv[i].w, wv[j].w, acc[i * 4 + j]);
                }
        }
        __syncthreads();
    }
#pragma unroll
    for (int i = 0; i < 4; ++i)
#pragma unroll
        for (int j = 0; j < 4; ++j) {
            int tt = t0 + tg * 4 + i;
            int aa = ag * 4 + j;
            g_psi[((size_t)b * ATT + aa) * T + tt] = acc[i * 4 + j] + bpsi[aa];
        }
}

// ---------------- persistent mega kernel ----------------
__global__ void __launch_bounds__(NTH, 1) k_mega(
        const int* __restrict__ x, const float* __restrict__ h,
        const float* __restrict__ Wih0, const float* __restrict__ Whh0,
        const float* __restrict__ bih0, const float* __restrict__ bhh0,
        const float* __restrict__ Wih1, const float* __restrict__ Whh1,
        const float* __restrict__ bih1, const float* __restrict__ bhh1,
        const float* __restrict__ Wphi, const float* __restrict__ bphi,
        const float* __restrict__ Wcd,  const float* __restrict__ bcd,
        float* __restrict__ out)
{
    extern __shared__ char smraw[];
    SmAll* sm = (SmAll*)smraw;

    int cta = blockIdx.x;
    int tid = threadIdx.x;
    unsigned phase = 0;
    if (tid == 0) phase = g_epoch;

    // mappings
    int c64  = (cta < 64) ? cta : cta - 64;  // within 64-group
    int rg4  = c64 >> 2;                     // 16 row-groups (K-split 4)
    int sp4  = c64 & 3;
    int rg8  = cta >> 3;                     // J3: 16 row-groups (K-split 8)
    int sp8  = cta & 7;

    // one-time weight staging
    if (cta < 64) {
        // Wa = Wih0 slice [k128][row128]
#pragma unroll 4
        for (int i = 0; i < 32; ++i) {
            int idx = i * 512 + tid;
            int k = idx & 127, r = idx >> 7;
            sm->Wa[k * 128 + r] = Wih0[(size_t)(rg4 * 128 + r) * 576 + 64 + sp4 * 128 + k];
        }
    } else if (cta < 128) {
        // Wa = Whh0 slice, Wb = Whh1 slice
#pragma unroll 4
        for (int i = 0; i < 32; ++i) {
            int idx = i * 512 + tid;
            int k = idx & 127, r = idx >> 7;
            sm->Wa[k * 128 + r] = Whh0[(size_t)(rg4 * 128 + r) * 512 + sp4 * 128 + k];
            sm->Wb[k * 128 + r] = Whh1[(size_t)(rg4 * 128 + r) * 512 + sp4 * 128 + k];
        }
    }
    if (cta < 128) {
        // Wc = Wih1 slice [k64][row128]
#pragma unroll 4
        for (int i = 0; i < 16; ++i) {
            int idx = i * 512 + tid;
            int k = idx & 63, r = idx >> 6;
            sm->Wc[k * 128 + r] = Wih1[(size_t)(rg8 * 128 + r) * 512 + sp8 * 64 + k];
        }
    }

    // init states + ctx = h[:,0,:]
    if (cta < B) {
        int b = cta;
        g_ctx[b * S + tid] = h[(size_t)b * T * H2D + tid];
        g_h1[b * S + tid]  = 0.f;
        g_h2[b * S + tid]  = 0.f;
        g_c1[b * S + tid]  = 0.f;
        g_c2[b * S + tid]  = 0.f;
    }
    gbar(phase, cta);

    for (int t = 0; t < NSTEP; ++t) {
        // P1: attn[t-1] (cta 0-63) || J2 = Whh0 @ h1[t-1] (cta 64-127)
        if (cta >= 64 && cta < 128) {
            lstm_gemm<128>(sm->Wa, sm->u.Bs, tid, rg4 * 128, 4 + sp4, g_h1, sp4 * 128);
        } else if (cta < 64 && t > 0) {
            attn_phase(&sm->u.a, cta, tid, bih1, bhh1, Wphi, bphi, Wcd, bcd, out, t - 1);
        }
        gbar(phase, cta);

        // P2: J1 = Wih0 @ ctx[t-1] (cta 0-63) || J4 = Whh1 @ h2[t-1] (cta 64-127)
        if (cta < 64) {
            lstm_gemm<128>(sm->Wa, sm->u.Bs, tid, rg4 * 128, sp4, g_ctx, sp4 * 128);
        } else if (cta < 128) {
            lstm_gemm<128>(sm->Wb, sm->u.Bs, tid, rg4 * 128, 16 + sp4, g_h2, sp4 * 128);
        }
        gbar(phase, cta);

        // P3: epi0 -> h1[t]
        epi0(cta, tid, Wih0, bih0, bhh0, x, t);
        gbar(phase, cta);

        // P4: J3 = Wih1 @ h1[t] (all 128 CTAs, K=64)
        if (cta < 128) {
            lstm_gemm<64>(sm->Wc, sm->u.Bs, tid, rg8 * 128, 8 + sp8, g_h1, sp8 * 64);
        }
        gbar(phase, cta);
    }

    // tail: attn for the final step
    if (cta < 64)
        attn_phase(&sm->u.a, cta, tid, bih1, bhh1, Wphi, bphi, Wcd, bcd, out, NSTEP - 1);
}

// ---------------- launcher ----------------
extern "C" void kernel_launch(void* const* d_in, const int* in_sizes, int n_in,
                              void* d_out, int out_size)
{
    const int*   x    = (const int*)d_in[0];
    const float* h    = (const float*)d_in[1];
    const float* Wih0 = (const float*)d_in[2];
    const float* Whh0 = (const float*)d_in[3];
    const float* bih0 = (const float*)d_in[4];
    const float* bhh0 = (const float*)d_in[5];
    const float* Wih1 = (const float*)d_in[6];
    const float* Whh1 = (const float*)d_in[7];
    const float* bih1 = (const float*)d_in[8];
    const float* bhh1 = (const float*)d_in[9];
    const float* Wphi = (const float*)d_in[10];
    const float* bphi = (const float*)d_in[11];
    const float* Wpsi = (const float*)d_in[12];
    const float* bpsi = (const float*)d_in[13];
    const float* Wcd  = (const float*)d_in[14];
    const float* bcd  = (const float*)d_in[15];
    float* out = (float*)d_out;

    static int smem_set = 0;
    if (!smem_set) {
        cudaFuncSetAttribute(k_mega, cudaFuncAttributeMaxDynamicSharedMemorySize,
                             (int)sizeof(SmAll));
        smem_set = 1;
    }

    k_h16<<<(B * T * H2D) / (256 * 8), 256>>>(h);
    k_psi<<<dim3(T / 32, B), 256>>>(h, Wpsi, bpsi);
    k_mega<<<GRID, NTH, sizeof(SmAll)>>>(x, h, Wih0, Whh0, bih0, bhh0,
                                         Wih1, Whh1, bih1, bhh1,
                                         Wphi, bphi, Wcd, bcd, out);
}

// round 9
// speedup vs baseline: 2.6445x; 1.1121x over previous
#include <cuda_runtime.h>
#include <cuda_fp16.h>
#include <math.h>

#define B     64
#define T     512
#define NSTEP 128
#define S     512
#define H2D   512
#define ATT   128
#define NCLS  64
#define GRID  148
#define NTH   512

typedef unsigned long long ull;

// ---------------- scratch (static device globals; no allocation) ----------------
__device__ __half g_psi16[B * ATT * T];      // TRANSPOSED fp16: [b][a][tt]
__device__ __half g_h16[B * T * H2D];        // fp16 copy of h for ctx reduction
__device__ __half g_Wphi16[ATT * S];
__device__ __half g_Wcd16[NCLS * (S + H2D)];
__device__ float  g_part[20 * 64 * 2048];    // [(slot*64+b)*2048 + row]
__device__ float  g_h1[B * S];
__device__ float  g_h2[B * S];
__device__ float  g_c1[B * S];
__device__ float  g_c2[B * S];
__device__ float  g_ctx[B * H2D];
__device__ unsigned g_cnt1[8];
__device__ unsigned g_cnt2;
__device__ volatile unsigned g_epoch;

__device__ __forceinline__ float tanh_fast(float v)
{
    float r;
    asm("tanh.approx.f32 %0, %1;" : "=f"(r) : "f"(v));
    return r;
}
__device__ __forceinline__ float sigf(float v) { return 0.5f * tanh_fast(0.5f * v) + 0.5f; }

__device__ __forceinline__ ull fma2(ull a, ull b, ull c)
{
    ull d;
    asm("fma.rn.f32x2 %0, %1, %2, %3;" : "=l"(d) : "l"(a), "l"(b), "l"(c));
    return d;
}
__device__ __forceinline__ ull dup2(float a)
{
    ull d;
    asm("mov.b64 %0, {%1, %1};" : "=l"(d) : "f"(a));
    return d;
}
__device__ __forceinline__ float pick(ull u, int hi)
{
    float2 f = *(float2*)&u;
    return hi ? f.y : f.x;
}

// -------- two-level grid barrier (148 co-resident CTAs) ------------------------
__device__ __forceinline__ void gbar(unsigned& phase, int cta)
{
    __syncthreads();
    if (threadIdx.x == 0) {
        ++phase;
        __threadfence();
        int grp = cta & 7;
        unsigned gsz = 18u + (grp < 4 ? 1u : 0u);   // 148 = 4*19 + 4*18
        if (atomicAdd(&g_cnt1[grp], 1u) == gsz - 1u) {
            g_cnt1[grp] = 0u;
            __threadfence();
            if (atomicAdd(&g_cnt2, 1u) == 7u) {
                g_cnt2 = 0u;
                __threadfence();
                g_epoch = phase;
            } else {
                while (g_epoch != phase) {}
            }
        } else {
            while (g_epoch != phase) {}
        }
        __threadfence();
    }
    __syncthreads();
}

// ---------------- smem ----------------
struct SmAttn {
    __align__(16) float part[16][520];
    __align__(16) float vec[1024];
    __align__(16) float phi[ATT];
    __align__(16) float al[T];
    __align__(16) float red[40];
};
struct SmAll {
    float Wa[128 * 128];    // cta<64: Wih0 slice (J1) | cta 64-127: Whh0 slice (J2)
    float Wb[128 * 128];    // cta 64-127: Whh1 slice (J4)
    float Wc[64 * 128];     // all 128: Wih1 slice (J3, K=64)
    union { __align__(16) float Bs[128 * 72]; SmAttn a; } u;
};

// -------- GEMM: 128 gate rows x 64 batches x K=KT; thread tile 4r x 4b ----------
template<int KT>
__device__ __forceinline__ void lstm_gemm(const float* __restrict__ As,
        float* __restrict__ Bs, int tid, int rowBase, int slot,
        const float* __restrict__ z, int koff)
{
#pragma unroll
    for (int i = 0; i < (KT * 64) / 512; ++i) {
        int idx = i * 512 + tid;
        int k = idx % KT, b = idx / KT;
        Bs[k * 72 + b] = z[b * 512 + koff + k];
    }
    __syncthreads();

    int rt = tid >> 4;          // rows rt*4..+3
    int bt = tid & 15;          // batches bt*4..+3
    const float* Ab = As + rt * 4;

    ull acc[4][2];
#pragma unroll
    for (int i = 0; i < 4; ++i) { acc[i][0] = 0ull; acc[i][1] = 0ull; }

#pragma unroll 8
    for (int k = 0; k < KT; ++k) {
        float4 a = *(const float4*)&Ab[k * 128];
        ulonglong2 bv = *(const ulonglong2*)&Bs[k * 72 + bt * 4];
        ull d;
        d = dup2(a.x); acc[0][0] = fma2(d, bv.x, acc[0][0]); acc[0][1] = fma2(d, bv.y, acc[0][1]);
        d = dup2(a.y); acc[1][0] = fma2(d, bv.x, acc[1][0]); acc[1][1] = fma2(d, bv.y, acc[1][1]);
        d = dup2(a.z); acc[2][0] = fma2(d, bv.x, acc[2][0]); acc[2][1] = fma2(d, bv.y, acc[2][1]);
        d = dup2(a.w); acc[3][0] = fma2(d, bv.x, acc[3][0]); acc[3][1] = fma2(d, bv.y, acc[3][1]);
    }

    int row0 = rowBase + rt * 4;
#pragma unroll
    for (int j = 0; j < 4; ++j) {
        int b = bt * 4 + j;
        int p = j >> 1, hi = j & 1;
        float4 v = make_float4(pick(acc[0][p], hi), pick(acc[1][p], hi),
                               pick(acc[2][p], hi), pick(acc[3][p], hi));
        *(float4*)&g_part[(size_t)(slot * 64 + b) * 2048 + row0] = v;
    }
}

// -------- LSTM0 epilogue WIDE: 128 CTAs = (batch, u-half); slot-split pairs -----
__device__ __forceinline__ void epi0(int cta, int tid,
        const float* __restrict__ Wih0,
        const float* __restrict__ bih, const float* __restrict__ bhh,
        const int* __restrict__ x, int t)
{
    if (cta >= 128) return;
    int b    = cta & 63;
    int half = cta >> 6;
    int u    = half * 256 + (tid >> 1);
    int sh   = (tid & 1) * 4;            // this thread's 4 K-slots
    float pre[4];
#pragma unroll
    for (int g = 0; g < 4; ++g) {
        int row = g * 512 + u;
        float s = 0.f;
#pragma unroll
        for (int sp = 0; sp < 4; ++sp)
            s += g_part[(size_t)((sh + sp) * 64 + b) * 2048 + row];
        pre[g] = s;
    }
#pragma unroll
    for (int g = 0; g < 4; ++g)
        pre[g] += __shfl_xor_sync(0xffffffffu, pre[g], 1);
    if ((tid & 1) == 0) {
        int cls = x[b * NSTEP + t];
#pragma unroll
        for (int g = 0; g < 4; ++g) {
            int row = g * 512 + u;
            pre[g] += bih[row] + bhh[row] + Wih0[(size_t)row * 576 + cls];
        }
        float co = g_c1[b * S + u];
        float cn = sigf(pre[1]) * co + sigf(pre[0]) * tanh_fast(pre[2]);
        float hn = sigf(pre[3]) * tanh_fast(cn);
        g_c1[b * S + u] = cn;
        g_h1[b * S + u] = hn;
    }
}

// -------- fused LSTM1-epilogue (slots 8-19) + attention + projection ------------
__device__ __forceinline__ void attn_phase(SmAttn* a, int cta, int tid,
        const float* __restrict__ bih1, const float* __restrict__ bhh1,
        const float* __restrict__ bphi, const float* __restrict__ bcd,
        float* __restrict__ out, int t)
{
    int b    = cta;
    int wid  = tid >> 5;
    int lane = tid & 31;

    // ---- LSTM1 epilogue ----
    {
        int u = tid;
        float pre[4];
#pragma unroll
        for (int g = 0; g < 4; ++g) {
            int row = g * 512 + u;
            float s = bih1[row] + bhh1[row];
#pragma unroll
            for (int sp = 8; sp < 20; ++sp)
                s += g_part[(size_t)(sp * 64 + b) * 2048 + row];
            pre[g] = s;
        }
        float co = g_c2[b * S + u];
        float cn = sigf(pre[1]) * co + sigf(pre[0]) * tanh_fast(pre[2]);
        float hn = sigf(pre[3]) * tanh_fast(cn);
        g_c2[b * S + u] = cn;
        g_h2[b * S + u] = hn;
        a->vec[u] = hn;
    }
    __syncthreads();

    // ---- phi = Wphi16 @ h2 + bphi (16 warps x 8 rows, fp16 weights) ----
#pragma unroll
    for (int i = 0; i < 8; ++i) {
        int aa = wid * 8 + i;
        const __half* wr = g_Wphi16 + aa * S;
        float sum = 0.f;
#pragma unroll
        for (int it = 0; it < 2; ++it) {
            int idx = it * 256 + lane * 8;
            uint4 w = *(const uint4*)&wr[idx];
            const __half2* wp = (const __half2*)&w;
            float4 v0 = *(const float4*)&a->vec[idx];
            float4 v1 = *(const float4*)&a->vec[idx + 4];
            float2 f0 = __half22float2(wp[0]);
            float2 f1 = __half22float2(wp[1]);
            float2 f2 = __half22float2(wp[2]);
            float2 f3 = __half22float2(wp[3]);
            sum = fmaf(f0.x, v0.x, sum); sum = fmaf(f0.y, v0.y, sum);
            sum = fmaf(f1.x, v0.z, sum); sum = fmaf(f1.y, v0.w, sum);
            sum = fmaf(f2.x, v1.x, sum); sum = fmaf(f2.y, v1.y, sum);
            sum = fmaf(f3.x, v1.z, sum); sum = fmaf(f3.y, v1.w, sum);
        }
#pragma unroll
        for (int o = 16; o > 0; o >>= 1) sum += __shfl_xor_sync(0xffffffffu, sum, o);
        if (lane == 0) a->phi[aa] = sum + bphi[aa];
    }
    __syncthreads();

    // ---- e[tt] via fp16 transposed psi: 8 a-groups x 64 tt-threads (8 tt each) --
    {
        int aw = tid >> 6;           // a-group 0..7 (16 a's each)
        int q  = tid & 63;           // tt octet q*8..+7
        const __half* pb = g_psi16 + ((size_t)b * ATT + aw * 16) * T + q * 8;
        float acc[8];
#pragma unroll
        for (int i = 0; i < 8; ++i) acc[i] = 0.f;
#pragma unroll 4
        for (int ai = 0; ai < 16; ++ai) {
            float pa = a->phi[aw * 16 + ai];
            uint4 u = *(const uint4*)&pb[(size_t)ai * T];
            const __half2* hp = (const __half2*)&u;
#pragma unroll
            for (int j = 0; j < 4; ++j) {
                float2 f = __half22float2(hp[j]);
                acc[j * 2 + 0] = fmaf(pa, f.x, acc[j * 2 + 0]);
                acc[j * 2 + 1] = fmaf(pa, f.y, acc[j * 2 + 1]);
            }
        }
        *(float4*)&a->part[aw][q * 8]     = make_float4(acc[0], acc[1], acc[2], acc[3]);
        *(float4*)&a->part[aw][q * 8 + 4] = make_float4(acc[4], acc[5], acc[6], acc[7]);
    }
    __syncthreads();

    // ---- softmax ----
    float e = 0.f;
#pragma unroll
    for (int r = 0; r < 8; ++r) e += a->part[r][tid];
    float m = e;
#pragma unroll
    for (int o = 16; o > 0; o >>= 1) m = fmaxf(m, __shfl_xor_sync(0xffffffffu, m, o));
    if (lane == 0) a->red[wid] = m;
    __syncthreads();
    if (tid == 0) {
        float mm = a->red[0];
        for (int i = 1; i < 16; ++i) mm = fmaxf(mm, a->red[i]);
        a->red[16] = mm;
    }
    __syncthreads();
    m = a->red[16];
    float ex = __expf(e - m);
    a->al[tid] = ex;
    float ssum = ex;
#pragma unroll
    for (int o = 16; o > 0; o >>= 1) ssum += __shfl_xor_sync(0xffffffffu, ssum, o);
    if (lane == 0) a->red[wid] = ssum;
    __syncthreads();
    if (tid == 0) {
        float s = 0.f;
        for (int i = 0; i < 16; ++i) s += a->red[i];
        a->red[17] = 1.f / s;
    }
    __syncthreads();
    float inv = a->red[17];

    // ---- ctx via fp16 h: 16 warps over tt, each lane 16 dims ----
    {
        const __half* hb = g_h16 + (size_t)b * T * H2D;
        float acc[16];
#pragma unroll
        for (int i = 0; i < 16; ++i) acc[i] = 0.f;
#pragma unroll 4
        for (int tt = wid * 32; tt < wid * 32 + 32; ++tt) {
            float av = a->al[tt];
            const __half* hr = hb + (size_t)tt * H2D + lane * 8;
            uint4 u0 = *(const uint4*)hr;
            uint4 u1 = *(const uint4*)(hr + 256);
            const __half2* p0 = (const __half2*)&u0;
            const __half2* p1 = (const __half2*)&u1;
#pragma unroll
            for (int j = 0; j < 4; ++j) {
                float2 f0 = __half22float2(p0[j]);
                float2 f1 = __half22float2(p1[j]);
                acc[j * 2 + 0] = fmaf(av, f0.x, acc[j * 2 + 0]);
                acc[j * 2 + 1] = fmaf(av, f0.y, acc[j * 2 + 1]);
                acc[8 + j * 2 + 0] = fmaf(av, f1.x, acc[8 + j * 2 + 0]);
                acc[8 + j * 2 + 1] = fmaf(av, f1.y, acc[8 + j * 2 + 1]);
            }
        }
#pragma unroll
        for (int j = 0; j < 2; ++j) {
            *(float4*)&a->part[wid][j * 256 + lane * 8]     =
                make_float4(acc[j * 8 + 0], acc[j * 8 + 1], acc[j * 8 + 2], acc[j * 8 + 3]);
            *(float4*)&a->part[wid][j * 256 + lane * 8 + 4] =
                make_float4(acc[j * 8 + 4], acc[j * 8 + 5], acc[j * 8 + 6], acc[j * 8 + 7]);
        }
    }
    __syncthreads();
    {
        float cv = 0.f;
#pragma unroll
        for (int w = 0; w < 16; ++w) cv += a->part[w][tid];
        cv *= inv;
        a->vec[S + tid] = cv;
        g_ctx[b * H2D + tid] = cv;
    }
    __syncthreads();

    // ---- out = Wcd16 @ [h2; ctx] + bcd (16 warps x 4 classes, fp16 weights) ----
#pragma unroll
    for (int i = 0; i < 4; ++i) {
        int c = wid * 4 + i;
        const __half* wr = g_Wcd16 + c * (S + H2D);
        float sum = 0.f;
#pragma unroll
        for (int it = 0; it < 4; ++it) {
            int idx = it * 256 + lane * 8;
            uint4 w = *(const uint4*)&wr[idx];
            const __half2* wp = (const __half2*)&w;
            float4 v0 = *(const float4*)&a->vec[idx];
            float4 v1 = *(const float4*)&a->vec[idx + 4];
            float2 f0 = __half22float2(wp[0]);
            float2 f1 = __half22float2(wp[1]);
            float2 f2 = __half22float2(wp[2]);
            float2 f3 = __half22float2(wp[3]);
            sum = fmaf(f0.x, v0.x, sum); sum = fmaf(f0.y, v0.y, sum);
            sum = fmaf(f1.x, v0.z, sum); sum = fmaf(f1.y, v0.w, sum);
            sum = fmaf(f2.x, v1.x, sum); sum = fmaf(f2.y, v1.y, sum);
            sum = fmaf(f3.x, v1.z, sum); sum = fmaf(f3.y, v1.w, sum);
        }
#pragma unroll
        for (int o = 16; o > 0; o >>= 1) sum += __shfl_xor_sync(0xffffffffu, sum, o);
        if (lane == 0) out[((size_t)b * NSTEP + t) * NCLS + c] = sum + bcd[c];
    }
    __syncthreads();
}

// ---------------- setup kernels ----------------
__global__ void k_h16(const float* __restrict__ h)
{
    size_t i = ((size_t)blockIdx.x * 256 + threadIdx.x) * 8;
    float4 v0 = *(const float4*)&h[i];
    float4 v1 = *(const float4*)&h[i + 4];
    __half2 o[4];
    o[0] = __floats2half2_rn(v0.x, v0.y);
    o[1] = __floats2half2_rn(v0.z, v0.w);
    o[2] = __floats2half2_rn(v1.x, v1.y);
    o[3] = __floats2half2_rn(v1.z, v1.w);
    *(uint4*)&g_h16[i] = *(uint4*)o;
}

__global__ void k_cvt(const float* __restrict__ Wphi, const float* __restrict__ Wcd)
{
    int i = blockIdx.x * 256 + threadIdx.x;
    g_Wphi16[i] = __float2half_rn(Wphi[i]);
    g_Wcd16[i]  = __float2half_rn(Wcd[i]);
}

// psi precompute -> fp16 transposed [b][a][tt]
__global__ void k_psi(const float* __restrict__ h,
                      const float* __restrict__ Wpsi,
                      const float* __restrict__ bpsi)
{
    __shared__ __align__(16) float hs[32][36];
    __shared__ __align__(16) float ws[128][36];
    int b   = blockIdx.y;
    int t0  = blockIdx.x * 32;
    int tid = threadIdx.x;
    int tg  = tid & 7;
    int ag  = tid >> 3;

    float acc[16];
#pragma unroll
    for (int i = 0; i < 16; ++i) acc[i] = 0.f;

    for (int dc = 0; dc < H2D; dc += 32) {
#pragma unroll
        for (int i = 0; i < 4; ++i) {
            int lin = tid + i * 256;
            int r = lin >> 5, c = lin & 31;
            hs[r][c] = h[((size_t)b * T + t0 + r) * H2D + dc + c];
        }
#pragma unroll
        for (int i = 0; i < 16; ++i) {
            int lin = tid + i * 256;
            int r = lin >> 5, c = lin & 31;
            ws[r][c] = Wpsi[r * H2D + dc + c];
        }
        __syncthreads();
#pragma unroll
        for (int k = 0; k < 32; k += 4) {
            float4 hv[4], wv[4];
#pragma unroll
            for (int j = 0; j < 4; ++j) hv[j] = *(const float4*)&hs[tg * 4 + j][k];
#pragma unroll
            for (int j = 0; j < 4; ++j) wv[j] = *(const float4*)&ws[ag * 4 + j][k];
#pragma unroll
            for (int i = 0; i < 4; ++i)
#pragma unroll
                for (int j = 0; j < 4; ++j) {
                    acc[i * 4 + j] = fmaf(hv[i].x, wv[j].x, acc[i * 4 + j]);
                    acc[i * 4 + j] = fmaf(hv[i].y, wv[j].y, acc[i * 4 + j]);
                    acc[i * 4 + j] = fmaf(hv[i].z, wv[j].z, acc[i * 4 + j]);
                    acc[i * 4 + j] = fmaf(hv[i].w, wv[j].w, acc[i * 4 + j]);
                }
        }
        __syncthreads();
    }
#pragma unroll
    for (int i = 0; i < 4; ++i)
#pragma unroll
        for (int j = 0; j < 4; ++j) {
            int tt = t0 + tg * 4 + i;
            int aa = ag * 4 + j;
            g_psi16[((size_t)b * ATT + aa) * T + tt] = __float2half_rn(acc[i * 4 + j] + bpsi[aa]);
        }
}

// ---------------- persistent mega kernel ----------------
__global__ void __launch_bounds__(NTH, 1) k_mega(
        const int* __restrict__ x, const float* __restrict__ h,
        const float* __restrict__ Wih0, const float* __restrict__ Whh0,
        const float* __restrict__ bih0, const float* __restrict__ bhh0,
        const float* __restrict__ Wih1, const float* __restrict__ Whh1,
        const float* __restrict__ bih1, const float* __restrict__ bhh1,
        const float* __restrict__ bphi, const float* __restrict__ bcd,
        float* __restrict__ out)
{
    extern __shared__ char smraw[];
    SmAll* sm = (SmAll*)smraw;

    int cta = blockIdx.x;
    int tid = threadIdx.x;
    unsigned phase = 0;
    if (tid == 0) phase = g_epoch;

    int c64  = (cta < 64) ? cta : cta - 64;
    int rg4  = c64 >> 2;
    int sp4  = c64 & 3;
    int rg8  = cta >> 3;
    int sp8  = cta & 7;

    // one-time weight staging
    if (cta < 64) {
#pragma unroll 4
        for (int i = 0; i < 32; ++i) {
            int idx = i * 512 + tid;
            int k = idx & 127, r = idx >> 7;
            sm->Wa[k * 128 + r] = Wih0[(size_t)(rg4 * 128 + r) * 576 + 64 + sp4 * 128 + k];
        }
    } else if (cta < 128) {
#pragma unroll 4
        for (int i = 0; i < 32; ++i) {
            int idx = i * 512 + tid;
            int k = idx & 127, r = idx >> 7;
            sm->Wa[k * 128 + r] = Whh0[(size_t)(rg4 * 128 + r) * 512 + sp4 * 128 + k];
            sm->Wb[k * 128 + r] = Whh1[(size_t)(rg4 * 128 + r) * 512 + sp4 * 128 + k];
        }
    }
    if (cta < 128) {
#pragma unroll 4
        for (int i = 0; i < 16; ++i) {
            int idx = i * 512 + tid;
            int k = idx & 63, r = idx >> 6;
            sm->Wc[k * 128 + r] = Wih1[(size_t)(rg8 * 128 + r) * 512 + sp8 * 64 + k];
        }
    }

    // init states + ctx = h[:,0,:]
    if (cta < B) {
        int b = cta;
        g_ctx[b * S + tid] = h[(size_t)b * T * H2D + tid];
        g_h1[b * S + tid]  = 0.f;
        g_h2[b * S + tid]  = 0.f;
        g_c1[b * S + tid]  = 0.f;
        g_c2[b * S + tid]  = 0.f;
    }
    gbar(phase, cta);

    for (int t = 0; t < NSTEP; ++t) {
        // P1: attn(t-1) [0-63] || J2 = Whh0 @ h1[t-1] [64-127]
        if (cta >= 64 && cta < 128) {
            lstm_gemm<128>(sm->Wa, sm->u.Bs, tid, rg4 * 128, 4 + sp4, g_h1, sp4 * 128);
        } else if (cta < 64 && t > 0) {
            attn_phase(&sm->u.a, cta, tid, bih1, bhh1, bphi, bcd, out, t - 1);
        }
        gbar(phase, cta);

        // P2: J1 = Wih0 @ ctx[t-1] [0-63] || J4 = Whh1 @ h2[t-1] [64-127]
        if (cta < 64) {
            lstm_gemm<128>(sm->Wa, sm->u.Bs, tid, rg4 * 128, sp4, g_ctx, sp4 * 128);
        } else if (cta < 128) {
            lstm_gemm<128>(sm->Wb, sm->u.Bs, tid, rg4 * 128, 16 + sp4, g_h2, sp4 * 128);
        }
        gbar(phase, cta);

        // P3: epi0 (wide, 128 CTAs) -> h1[t]
        epi0(cta, tid, Wih0, bih0, bhh0, x, t);
        gbar(phase, cta);

        // P4: J3 = Wih1 @ h1[t] (128 CTAs, K=64)
        if (cta < 128) {
            lstm_gemm<64>(sm->Wc, sm->u.Bs, tid, rg8 * 128, 8 + sp8, g_h1, sp8 * 64);
        }
        gbar(phase, cta);
    }

    // tail: attn for the final step
    if (cta < 64)
        attn_phase(&sm->u.a, cta, tid, bih1, bhh1, bphi, bcd, out, NSTEP - 1);
}

// ---------------- launcher ----------------
extern "C" void kernel_launch(void* const* d_in, const int* in_sizes, int n_in,
                              void* d_out, int out_size)
{
    const int*   x    = (const int*)d_in[0];
    const float* h    = (const float*)d_in[1];
    const float* Wih0 = (const float*)d_in[2];
    const float* Whh0 = (const float*)d_in[3];
    const float* bih0 = (const float*)d_in[4];
    const float* bhh0 = (const float*)d_in[5];
    const float* Wih1 = (const float*)d_in[6];
    const float* Whh1 = (const float*)d_in[7];
    const float* bih1 = (const float*)d_in[8];
    const float* bhh1 = (const float*)d_in[9];
    const float* Wphi = (const float*)d_in[10];
    const float* bphi = (const float*)d_in[11];
    const float* Wpsi = (const float*)d_in[12];
    const float* bpsi = (const float*)d_in[13];
    const float* Wcd  = (const float*)d_in[14];
    const float* bcd  = (const float*)d_in[15];
    float* out = (float*)d_out;

    static int smem_set = 0;
    if (!smem_set) {
        cudaFuncSetAttribute(k_mega, cudaFuncAttributeMaxDynamicSharedMemorySize,
                             (int)sizeof(SmAll));
        smem_set = 1;
    }

    k_h16<<<(B * T * H2D) / (256 * 8), 256>>>(h);
    k_cvt<<<(ATT * S) / 256, 256>>>(Wphi, Wcd);
    k_psi<<<dim3(T / 32, B), 256>>>(h, Wpsi, bpsi);
    k_mega<<<GRID, NTH, sizeof(SmAll)>>>(x, h, Wih0, Whh0, bih0, bhh0,
                                         Wih1, Whh1, bih1, bhh1,
                                         bphi, bcd, out);
}

// round 11
// speedup vs baseline: 3.6708x; 1.3881x over previous
#include <cuda_runtime.h>
#include <cuda_fp16.h>
#include <math.h>

#define B     64
#define T     512
#define NSTEP 128
#define S     512
#define H2D   512
#define ATT   128
#define NCLS  64
#define GRID  148
#define NTH   512

// ---------------- scratch (static device globals; no allocation) ----------------
__device__ __half g_psi16[B * ATT * T];      // TRANSPOSED fp16: [b][a][tt]
__device__ __half g_h16[B * T * H2D];        // fp16 copy of h for ctx reduction
__device__ __half g_Wphi16[ATT * S];
__device__ __half g_Wcd16[NCLS * (S + H2D)];
__device__ float  g_part[20 * 64 * 2048];    // [(slot*64+b)*2048 + row]
__device__ __half g_h1[B * S];               // fp16 recurrent states
__device__ __half g_h2[B * S];
__device__ __half g_ctx[B * H2D];
__device__ float  g_c1[B * S];               // cell states stay fp32
__device__ float  g_c2[B * S];
__device__ unsigned g_cnt1[8];
__device__ unsigned g_cnt2;
__device__ volatile unsigned g_epoch;

__device__ __forceinline__ float tanh_fast(float v)
{
    float r;
    asm("tanh.approx.f32 %0, %1;" : "=f"(r) : "f"(v));
    return r;
}
__device__ __forceinline__ float sigf(float v) { return 0.5f * tanh_fast(0.5f * v) + 0.5f; }

// -------- two-level grid barrier (148 co-resident CTAs) ------------------------
__device__ __forceinline__ void gbar(unsigned& phase, int cta)
{
    __syncthreads();
    if (threadIdx.x == 0) {
        ++phase;
        __threadfence();
        int grp = cta & 7;
        unsigned gsz = 18u + (grp < 4 ? 1u : 0u);   // 148 = 4*19 + 4*18
        if (atomicAdd(&g_cnt1[grp], 1u) == gsz - 1u) {
            g_cnt1[grp] = 0u;
            __threadfence();
            if (atomicAdd(&g_cnt2, 1u) == 7u) {
                g_cnt2 = 0u;
                __threadfence();
                g_epoch = phase;
            } else {
                while (g_epoch != phase) {}
            }
        } else {
            while (g_epoch != phase) {}
        }
        __threadfence();
    }
    __syncthreads();
}

// ---------------- smem ----------------
struct SmAttn {
    __align__(16) float part[16][520];
    __align__(16) float vec[1024];
    __align__(16) float phi[ATT];
    __align__(16) float al[T];
    __align__(16) float red[40];
};
struct SmAll {
    __align__(16) __half Wa[128 * 136];   // J1 (cta<64) / J2 (cta 64-127), [row][K128+8]
    __align__(16) __half Wb[128 * 136];   // J4 (cta 64-127)
    __align__(16) __half Wc[128 * 72];    // J3 (all 128), [row][K64+8]
    union { __align__(16) __half As[64 * 136]; SmAttn a; } u;
};

// -------- tensor-core GEMM: D[64 b][128 rows] += A[64 b][KT] * W[128 rows][KT] --
// mma.m16n8k16: A = activations (M=batches), B = weights (N=gate rows), f32 accum
template<int KT>
__device__ __forceinline__ void mma_gemm(const __half* __restrict__ Wsm,
        __half* __restrict__ Asm, int tid, int rowBase, int slot,
        const __half* __restrict__ z, int koff)
{
    constexpr int PK = KT + 8;

    // stage activations fp16 [b][PK]
    if (KT == 128) {
        int b = tid >> 3, kq = (tid & 7) * 16;
        const uint4* src = (const uint4*)(z + b * 512 + koff + kq);
        *(uint4*)&Asm[b * PK + kq]     = src[0];
        *(uint4*)&Asm[b * PK + kq + 8] = src[1];
    } else {
        int b = tid >> 3, kq = (tid & 7) * 8;
        *(uint4*)&Asm[b * PK + kq] = *(const uint4*)(z + b * 512 + koff + kq);
    }
    __syncthreads();

    int T32 = tid & 31, w = tid >> 5;
    int tq = T32 & 3, tr = T32 >> 2;
    int bBase = (w & 3) * 16;            // batch tile (M)
    int rBase = (w >> 2) * 32;           // gate-row tile (N, 4 atoms of 8)

    float d[4][4];
#pragma unroll
    for (int i = 0; i < 4; ++i)
#pragma unroll
        for (int j = 0; j < 4; ++j) d[i][j] = 0.f;

    const __half* Arow  = Asm + (bBase + tr) * PK;
    const __half* Arow8 = Arow + 8 * PK;

#pragma unroll
    for (int ks = 0; ks < KT / 16; ++ks) {
        int k0 = ks * 16;
        unsigned a0 = *(const unsigned*)&Arow [k0 + 2 * tq];
        unsigned a1 = *(const unsigned*)&Arow8[k0 + 2 * tq];
        unsigned a2 = *(const unsigned*)&Arow [k0 + 8 + 2 * tq];
        unsigned a3 = *(const unsigned*)&Arow8[k0 + 8 + 2 * tq];
#pragma unroll
        for (int na = 0; na < 4; ++na) {
            const __half* Brow = Wsm + (rBase + na * 8 + tr) * PK;
            unsigned b0 = *(const unsigned*)&Brow[k0 + 2 * tq];
            unsigned b1 = *(const unsigned*)&Brow[k0 + 8 + 2 * tq];
            asm volatile(
                "mma.sync.aligned.m16n8k16.row.col.f32.f16.f16.f32 "
                "{%0,%1,%2,%3}, {%4,%5,%6,%7}, {%8,%9}, {%0,%1,%2,%3};"
                : "+f"(d[na][0]), "+f"(d[na][1]), "+f"(d[na][2]), "+f"(d[na][3])
                : "r"(a0), "r"(a1), "r"(a2), "r"(a3), "r"(b0), "r"(b1));
        }
    }

    // store: d[na][0,1] -> (b = bBase+tr, rows n0+2tq,+1); d[na][2,3] -> b+8
    int gr0 = rowBase + rBase;
#pragma unroll
    for (int na = 0; na < 4; ++na) {
        int rcol = gr0 + na * 8 + 2 * tq;
        *(float2*)&g_part[(size_t)(slot * 64 + bBase + tr) * 2048 + rcol] =
            make_float2(d[na][0], d[na][1]);
        *(float2*)&g_part[(size_t)(slot * 64 + bBase + tr + 8) * 2048 + rcol] =
            make_float2(d[na][2], d[na][3]);
    }
}

// -------- LSTM0 epilogue WIDE: 128 CTAs = (batch, u-half); slot-split pairs -----
__device__ __forceinline__ void epi0(int cta, int tid,
        const float* __restrict__ Wih0,
        const float* __restrict__ bih, const float* __restrict__ bhh,
        const int* __restrict__ x, int t)
{
    if (cta >= 128) return;
    int b    = cta & 63;
    int half = cta >> 6;
    int u    = half * 256 + (tid >> 1);
    int sh   = (tid & 1) * 4;
    float pre[4];
#pragma unroll
    for (int g = 0; g < 4; ++g) {
        int row = g * 512 + u;
        float s = 0.f;
#pragma unroll
        for (int sp = 0; sp < 4; ++sp)
            s += g_part[(size_t)((sh + sp) * 64 + b) * 2048 + row];
        pre[g] = s;
    }
#pragma unroll
    for (int g = 0; g < 4; ++g)
        pre[g] += __shfl_xor_sync(0xffffffffu, pre[g], 1);
    if ((tid & 1) == 0) {
        int cls = x[b * NSTEP + t];
#pragma unroll
        for (int g = 0; g < 4; ++g) {
            int row = g * 512 + u;
            pre[g] += bih[row] + bhh[row] + Wih0[(size_t)row * 576 + cls];
        }
        float co = g_c1[b * S + u];
        float cn = sigf(pre[1]) * co + sigf(pre[0]) * tanh_fast(pre[2]);
        float hn = sigf(pre[3]) * tanh_fast(cn);
        g_c1[b * S + u] = cn;
        g_h1[b * S + u] = __float2half_rn(hn);
    }
}

// -------- fused LSTM1-epilogue (slots 8-19) + attention + projection ------------
__device__ __forceinline__ void attn_phase(SmAttn* a, int cta, int tid,
        const float* __restrict__ bih1, const float* __restrict__ bhh1,
        const float* __restrict__ bphi, const float* __restrict__ bcd,
        float* __restrict__ out, int t)
{
    int b    = cta;
    int wid  = tid >> 5;
    int lane = tid & 31;

    // ---- LSTM1 epilogue ----
    {
        int u = tid;
        float pre[4];
#pragma unroll
        for (int g = 0; g < 4; ++g) {
            int row = g * 512 + u;
            float s = bih1[row] + bhh1[row];
#pragma unroll
            for (int sp = 8; sp < 20; ++sp)
                s += g_part[(size_t)(sp * 64 + b) * 2048 + row];
            pre[g] = s;
        }
        float co = g_c2[b * S + u];
        float cn = sigf(pre[1]) * co + sigf(pre[0]) * tanh_fast(pre[2]);
        float hn = sigf(pre[3]) * tanh_fast(cn);
        g_c2[b * S + u] = cn;
        g_h2[b * S + u] = __float2half_rn(hn);
        a->vec[u] = hn;
    }
    __syncthreads();

    // ---- phi = Wphi16 @ h2 + bphi ----
#pragma unroll
    for (int i = 0; i < 8; ++i) {
        int aa = wid * 8 + i;
        const __half* wr = g_Wphi16 + aa * S;
        float sum = 0.f;
#pragma unroll
        for (int it = 0; it < 2; ++it) {
            int idx = it * 256 + lane * 8;
            uint4 w = *(const uint4*)&wr[idx];
            const __half2* wp = (const __half2*)&w;
            float4 v0 = *(const float4*)&a->vec[idx];
            float4 v1 = *(const float4*)&a->vec[idx + 4];
            float2 f0 = __half22float2(wp[0]);
            float2 f1 = __half22float2(wp[1]);
            float2 f2 = __half22float2(wp[2]);
            float2 f3 = __half22float2(wp[3]);
            sum = fmaf(f0.x, v0.x, sum); sum = fmaf(f0.y, v0.y, sum);
            sum = fmaf(f1.x, v0.z, sum); sum = fmaf(f1.y, v0.w, sum);
            sum = fmaf(f2.x, v1.x, sum); sum = fmaf(f2.y, v1.y, sum);
            sum = fmaf(f3.x, v1.z, sum); sum = fmaf(f3.y, v1.w, sum);
        }
#pragma unroll
        for (int o = 16; o > 0; o >>= 1) sum += __shfl_xor_sync(0xffffffffu, sum, o);
        if (lane == 0) a->phi[aa] = sum + bphi[aa];
    }
    __syncthreads();

    // ---- e[tt] via fp16 transposed psi ----
    {
        int aw = tid >> 6;
        int q  = tid & 63;
        const __half* pb = g_psi16 + ((size_t)b * ATT + aw * 16) * T + q * 8;
        float acc[8];
#pragma unroll
        for (int i = 0; i < 8; ++i) acc[i] = 0.f;
#pragma unroll 4
        for (int ai = 0; ai < 16; ++ai) {
            float pa = a->phi[aw * 16 + ai];
            uint4 u = *(const uint4*)&pb[(size_t)ai * T];
            const __half2* hp = (const __half2*)&u;
#pragma unroll
            for (int j = 0; j < 4; ++j) {
                float2 f = __half22float2(hp[j]);
                acc[j * 2 + 0] = fmaf(pa, f.x, acc[j * 2 + 0]);
                acc[j * 2 + 1] = fmaf(pa, f.y, acc[j * 2 + 1]);
            }
        }
        *(float4*)&a->part[aw][q * 8]     = make_float4(acc[0], acc[1], acc[2], acc[3]);
        *(float4*)&a->part[aw][q * 8 + 4] = make_float4(acc[4], acc[5], acc[6], acc[7]);
    }
    __syncthreads();

    // ---- softmax ----
    float e = 0.f;
#pragma unroll
    for (int r = 0; r < 8; ++r) e += a->part[r][tid];
    float m = e;
#pragma unroll
    for (int o = 16; o > 0; o >>= 1) m = fmaxf(m, __shfl_xor_sync(0xffffffffu, m, o));
    if (lane == 0) a->red[wid] = m;
    __syncthreads();
    if (tid == 0) {
        float mm = a->red[0];
        for (int i = 1; i < 16; ++i) mm = fmaxf(mm, a->red[i]);
        a->red[16] = mm;
    }
    __syncthreads();
    m = a->red[16];
    float ex = __expf(e - m);
    a->al[tid] = ex;
    float ssum = ex;
#pragma unroll
    for (int o = 16; o > 0; o >>= 1) ssum += __shfl_xor_sync(0xffffffffu, ssum, o);
    if (lane == 0) a->red[wid] = ssum;
    __syncthreads();
    if (tid == 0) {
        float s = 0.f;
        for (int i = 0; i < 16; ++i) s += a->red[i];
        a->red[17] = 1.f / s;
    }
    __syncthreads();
    float inv = a->red[17];

    // ---- ctx via fp16 h ----
    {
        const __half* hb = g_h16 + (size_t)b * T * H2D;
        float acc[16];
#pragma unroll
        for (int i = 0; i < 16; ++i) acc[i] = 0.f;
#pragma unroll 4
        for (int tt = wid * 32; tt < wid * 32 + 32; ++tt) {
            float av = a->al[tt];
            const __half* hr = hb + (size_t)tt * H2D + lane * 8;
            uint4 u0 = *(const uint4*)hr;
            uint4 u1 = *(const uint4*)(hr + 256);
            const __half2* p0 = (const __half2*)&u0;
            const __half2* p1 = (const __half2*)&u1;
#pragma unroll
            for (int j = 0; j < 4; ++j) {
                float2 f0 = __half22float2(p0[j]);
                float2 f1 = __half22float2(p1[j]);
                acc[j * 2 + 0] = fmaf(av, f0.x, acc[j * 2 + 0]);
                acc[j * 2 + 1] = fmaf(av, f0.y, acc[j * 2 + 1]);
                acc[8 + j * 2 + 0] = fmaf(av, f1.x, acc[8 + j * 2 + 0]);
                acc[8 + j * 2 + 1] = fmaf(av, f1.y, acc[8 + j * 2 + 1]);
            }
        }
#pragma unroll
        for (int j = 0; j < 2; ++j) {
            *(float4*)&a->part[wid][j * 256 + lane * 8]     =
                make_float4(acc[j * 8 + 0], acc[j * 8 + 1], acc[j * 8 + 2], acc[j * 8 + 3]);
            *(float4*)&a->part[wid][j * 256 + lane * 8 + 4] =
                make_float4(acc[j * 8 + 4], acc[j * 8 + 5], acc[j * 8 + 6], acc[j * 8 + 7]);
        }
    }
    __syncthreads();
    {
        float cv = 0.f;
#pragma unroll
        for (int w = 0; w < 16; ++w) cv += a->part[w][tid];
        cv *= inv;
        a->vec[S + tid] = cv;
        g_ctx[b * H2D + tid] = __float2half_rn(cv);
    }
    __syncthreads();

    // ---- out = Wcd16 @ [h2; ctx] + bcd ----
#pragma unroll
    for (int i = 0; i < 4; ++i) {
        int c = wid * 4 + i;
        const __half* wr = g_Wcd16 + c * (S + H2D);
        float sum = 0.f;
#pragma unroll
        for (int it = 0; it < 4; ++it) {
            int idx = it * 256 + lane * 8;
            uint4 w = *(const uint4*)&wr[idx];
            const __half2* wp = (const __half2*)&w;
            float4 v0 = *(const float4*)&a->vec[idx];
            float4 v1 = *(const float4*)&a->vec[idx + 4];
            float2 f0 = __half22float2(wp[0]);
            float2 f1 = __half22float2(wp[1]);
            float2 f2 = __half22float2(wp[2]);
            float2 f3 = __half22float2(wp[3]);
            sum = fmaf(f0.x, v0.x, sum); sum = fmaf(f0.y, v0.y, sum);
            sum = fmaf(f1.x, v0.z, sum); sum = fmaf(f1.y, v0.w, sum);
            sum = fmaf(f2.x, v1.x, sum); sum = fmaf(f2.y, v1.y, sum);
            sum = fmaf(f3.x, v1.z, sum); sum = fmaf(f3.y, v1.w, sum);
        }
#pragma unroll
        for (int o = 16; o > 0; o >>= 1) sum += __shfl_xor_sync(0xffffffffu, sum, o);
        if (lane == 0) out[((size_t)b * NSTEP + t) * NCLS + c] = sum + bcd[c];
    }
    __syncthreads();
}

// ---------------- setup kernels ----------------
__global__ void k_h16(const float* __restrict__ h)
{
    size_t i = ((size_t)blockIdx.x * 256 + threadIdx.x) * 8;
    float4 v0 = *(const float4*)&h[i];
    float4 v1 = *(const float4*)&h[i + 4];
    __half2 o[4];
    o[0] = __floats2half2_rn(v0.x, v0.y);
    o[1] = __floats2half2_rn(v0.z, v0.w);
    o[2] = __floats2half2_rn(v1.x, v1.y);
    o[3] = __floats2half2_rn(v1.z, v1.w);
    *(uint4*)&g_h16[i] = *(uint4*)o;
}

__global__ void k_cvt(const float* __restrict__ Wphi, const float* __restrict__ Wcd)
{
    int i = blockIdx.x * 256 + threadIdx.x;
    g_Wphi16[i] = __float2half_rn(Wphi[i]);
    g_Wcd16[i]  = __float2half_rn(Wcd[i]);
}

// psi precompute -> fp16 transposed [b][a][tt]
__global__ void k_psi(const float* __restrict__ h,
                      const float* __restrict__ Wpsi,
                      const float* __restrict__ bpsi)
{
    __shared__ __align__(16) float hs[32][36];
    __shared__ __align__(16) float ws[128][36];
    int b   = blockIdx.y;
    int t0  = blockIdx.x * 32;
    int tid = threadIdx.x;
    int tg  = tid & 7;
    int ag  = tid >> 3;

    float acc[16];
#pragma unroll
    for (int i = 0; i < 16; ++i) acc[i] = 0.f;

    for (int dc = 0; dc < H2D; dc += 32) {
#pragma unroll
        for (int i = 0; i < 4; ++i) {
            int lin = tid + i * 256;
            int r = lin >> 5, c = lin & 31;
            hs[r][c] = h[((size_t)b * T + t0 + r) * H2D + dc + c];
        }
#pragma unroll
        for (int i = 0; i < 16; ++i) {
            int lin = tid + i * 256;
            int r = lin >> 5, c = lin & 31;
            ws[r][c] = Wpsi[r * H2D + dc + c];
        }
        __syncthreads();
#pragma unroll
        for (int k = 0; k < 32; k += 4) {
            float4 hv[4], wv[4];
#pragma unroll
            for (int j = 0; j < 4; ++j) hv[j] = *(const float4*)&hs[tg * 4 + j][k];
#pragma unroll
            for (int j = 0; j < 4; ++j) wv[j] = *(const float4*)&ws[ag * 4 + j][k];
#pragma unroll
            for (int i = 0; i < 4; ++i)
#pragma unroll
                for (int j = 0; j < 4; ++j) {
                    acc[i * 4 + j] = fmaf(hv[i].x, wv[j].x, acc[i * 4 + j]);
                    acc[i * 4 + j] = fmaf(hv[i].y, wv[j].y, acc[i * 4 + j]);
                    acc[i * 4 + j] = fmaf(hv[i].z, wv[j].z, acc[i * 4 + j]);
                    acc[i * 4 + j] = fmaf(hv[i].w, wv[j].w, acc[i * 4 + j]);
                }
        }
        __syncthreads();
    }
#pragma unroll
    for (int i = 0; i < 4; ++i)
#pragma unroll
        for (int j = 0; j < 4; ++j) {
            int tt = t0 + tg * 4 + i;
            int aa = ag * 4 + j;
            g_psi16[((size_t)b * ATT + aa) * T + tt] = __float2half_rn(acc[i * 4 + j] + bpsi[aa]);
        }
}

// ---------------- persistent mega kernel ----------------
__global__ void __launch_bounds__(NTH, 1) k_mega(
        const int* __restrict__ x, const float* __restrict__ h,
        const float* __restrict__ Wih0, const float* __restrict__ Whh0,
        const float* __restrict__ bih0, const float* __restrict__ bhh0,
        const float* __restrict__ Wih1, const float* __restrict__ Whh1,
        const float* __restrict__ bih1, const float* __restrict__ bhh1,
        const float* __restrict__ bphi, const float* __restrict__ bcd,
        float* __restrict__ out)
{
    extern __shared__ char smraw[];
    SmAll* sm = (SmAll*)smraw;

    int cta = blockIdx.x;
    int tid = threadIdx.x;
    unsigned phase = 0;
    if (tid == 0) phase = g_epoch;

    int c64  = (cta < 64) ? cta : cta - 64;
    int rg4  = c64 >> 2;
    int sp4  = c64 & 3;
    int rg8  = cta >> 3;
    int sp8  = cta & 7;

    // one-time fp16 weight staging, layout [row][K+8]
    if (cta < 64) {
        int r = tid >> 2, kq = (tid & 3) * 32;
        const float* src = Wih0 + (size_t)(rg4 * 128 + r) * 576 + 64 + sp4 * 128 + kq;
#pragma unroll
        for (int j = 0; j < 32; ++j)
            sm->Wa[r * 136 + kq + j] = __float2half_rn(src[j]);
    } else if (cta < 128) {
        int r = tid >> 2, kq = (tid & 3) * 32;
        const float* s0 = Whh0 + (size_t)(rg4 * 128 + r) * 512 + sp4 * 128 + kq;
        const float* s1 = Whh1 + (size_t)(rg4 * 128 + r) * 512 + sp4 * 128 + kq;
#pragma unroll
        for (int j = 0; j < 32; ++j) {
            sm->Wa[r * 136 + kq + j] = __float2half_rn(s0[j]);
            sm->Wb[r * 136 + kq + j] = __float2half_rn(s1[j]);
        }
    }
    if (cta < 128) {
        int r = tid >> 2, kq = (tid & 3) * 16;
        const float* src = Wih1 + (size_t)(rg8 * 128 + r) * 512 + sp8 * 64 + kq;
#pragma unroll
        for (int j = 0; j < 16; ++j)
            sm->Wc[r * 72 + kq + j] = __float2half_rn(src[j]);
    }

    // init states + ctx = h[:,0,:]
    if (cta < B) {
        int b = cta;
        g_ctx[b * S + tid] = __float2half_rn(h[(size_t)b * T * H2D + tid]);
        g_h1[b * S + tid]  = __float2half_rn(0.f);
        g_h2[b * S + tid]  = __float2half_rn(0.f);
        g_c1[b * S + tid]  = 0.f;
        g_c2[b * S + tid]  = 0.f;
    }
    gbar(phase, cta);

    for (int t = 0; t < NSTEP; ++t) {
        // P1: attn(t-1) [0-63] || J2 = Whh0 @ h1[t-1] [64-127]
        if (cta >= 64 && cta < 128) {
            mma_gemm<128>(sm->Wa, sm->u.As, tid, rg4 * 128, 4 + sp4, g_h1, sp4 * 128);
        } else if (cta < 64 && t > 0) {
            attn_phase(&sm->u.a, cta, tid, bih1, bhh1, bphi, bcd, out, t - 1);
        }
        gbar(phase, cta);

        // P2: J1 = Wih0 @ ctx[t-1] [0-63] || J4 = Whh1 @ h2[t-1] [64-127]
        if (cta < 64) {
            mma_gemm<128>(sm->Wa, sm->u.As, tid, rg4 * 128, sp4, g_ctx, sp4 * 128);
        } else if (cta < 128) {
            mma_gemm<128>(sm->Wb, sm->u.As, tid, rg4 * 128, 16 + sp4, g_h2, sp4 * 128);
        }
        gbar(phase, cta);

        // P3: epi0 (wide, 128 CTAs) -> h1[t]
        epi0(cta, tid, Wih0, bih0, bhh0, x, t);
        gbar(phase, cta);

        // P4: J3 = Wih1 @ h1[t] (128 CTAs, K=64)
        if (cta < 128) {
            mma_gemm<64>(sm->Wc, sm->u.As, tid, rg8 * 128, 8 + sp8, g_h1, sp8 * 64);
        }
        gbar(phase, cta);
    }

    // tail: attn for the final step
    if (cta < 64)
        attn_phase(&sm->u.a, cta, tid, bih1, bhh1, bphi, bcd, out, NSTEP - 1);
}

// ---------------- launcher ----------------
extern "C" void kernel_launch(void* const* d_in, const int* in_sizes, int n_in,
                              void* d_out, int out_size)
{
    const int*   x    = (const int*)d_in[0];
    const float* h    = (const float*)d_in[1];
    const float* Wih0 = (const float*)d_in[2];
    const float* Whh0 = (const float*)d_in[3];
    const float* bih0 = (const float*)d_in[4];
    const float* bhh0 = (const float*)d_in[5];
    const float* Wih1 = (const float*)d_in[6];
    const float* Whh1 = (const float*)d_in[7];
    const float* bih1 = (const float*)d_in[8];
    const float* bhh1 = (const float*)d_in[9];
    const float* Wphi = (const float*)d_in[10];
    const float* bphi = (const float*)d_in[11];
    const float* Wpsi = (const float*)d_in[12];
    const float* bpsi = (const float*)d_in[13];
    const float* Wcd  = (const float*)d_in[14];
    const float* bcd  = (const float*)d_in[15];
    float* out = (float*)d_out;

    static int smem_set = 0;
    if (!smem_set) {
        cudaFuncSetAttribute(k_mega, cudaFuncAttributeMaxDynamicSharedMemorySize,
                             (int)sizeof(SmAll));
        smem_set = 1;
    }

    k_h16<<<(B * T * H2D) / (256 * 8), 256>>>(h);
    k_cvt<<<(ATT * S) / 256, 256>>>(Wphi, Wcd);
    k_psi<<<dim3(T / 32, B), 256>>>(h, Wpsi, bpsi);
    k_mega<<<GRID, NTH, sizeof(SmAll)>>>(x, h, Wih0, Whh0, bih0, bhh0,
                                         Wih1, Whh1, bih1, bhh1,
                                         bphi, bcd, out);
}